// round 1
// baseline (speedup 1.0000x reference)
#include <cuda_runtime.h>

#define T_LEN   8192
#define C_CH    256
#define B_SZ    8
#define TT      64      // time tile per block
#define CCHUNK  64      // K-chunk (input channels) staged in smem
#define LRELU_S 0.1f

// ---------------- device scratch (no allocations allowed) ----------------
__device__ float g_y[B_SZ * C_CH * T_LEN];          // 64 MB intermediate (post-lrelu stage-1 output)
__device__ float g_WtC[3 * 65536];                  // transposed weights [i][c][o]
__device__ float g_WtP[3 * 65536];
__device__ float g_WtF[3 * 65536];
__device__ float g_WtA[9 * 65536];                  // [i][k][c][o]

typedef unsigned long long ull;

__device__ __forceinline__ ull pack2(float lo, float hi) {
    ull r; asm("mov.b64 %0, {%1, %2};" : "=l"(r) : "f"(lo), "f"(hi)); return r;
}
__device__ __forceinline__ void fma2(ull& d, ull a, ull b) {
    // packed f32x2 FMA: 2x fp32 throughput on the fma pipe (PTX-only form)
    asm("fma.rn.f32x2 %0, %1, %2, %0;" : "+l"(d) : "l"(a), "l"(b));
}
__device__ __forceinline__ float lrelu(float v) { return fmaxf(v, LRELU_S * v); }
__device__ __forceinline__ float f_lo(ull v) { return __uint_as_float((unsigned)v); }
__device__ __forceinline__ float f_hi(ull v) { return __uint_as_float((unsigned)(v >> 32)); }

// ---------------- weight transpose / prep ----------------
__global__ void prep_kernel(const float* __restrict__ WC, const float* __restrict__ WP,
                            const float* __restrict__ WF, const float* __restrict__ WA) {
    int id = blockIdx.x * 256 + threadIdx.x;          // 3*256*256 = 196608 threads
    if (id >= 3 * 65536) return;
    int i = id >> 16;
    int r = id & 65535;
    int o = r >> 8;
    int c = r & 255;
    int src = i * 65536 + o * 256 + c;
    int dst = i * 65536 + c * 256 + o;
    g_WtC[dst] = WC[src];
    g_WtP[dst] = WP[src];
    g_WtF[dst] = WF[src];
#pragma unroll
    for (int k = 0; k < 3; ++k)
        g_WtA[(i * 3 + k) * 65536 + c * 256 + o] = WA[src * 3 + k];
}

// ---------------- stage 1: lrelu + gather + 3x conv1x1 + lrelu -> g_y ----------------
__global__ __launch_bounds__(256, 2)
void k1_kernel(const float* __restrict__ x, const float* __restrict__ dfac,
               const float* __restrict__ bC, const float* __restrict__ bP,
               const float* __restrict__ bF, int iter, float dilation) {
    extern __shared__ float sm[];
    float* s_xt = sm;            // [64][64]
    float* s_xp = sm + 4096;
    float* s_xf = sm + 8192;
    int*   s_ip = (int*)(sm + 12288);   // [64]
    int*   s_if = s_ip + 64;

    const float* WtC = g_WtC + iter * 65536;
    const float* WtP = g_WtP + iter * 65536;
    const float* WtF = g_WtF + iter * 65536;

    int tid = threadIdx.x;
    int t0  = blockIdx.x * TT;
    int b   = blockIdx.y;
    const float* xb = x + (size_t)b * C_CH * T_LEN;

    if (tid < TT) {
        int t = t0 + tid;
        float dil = dfac[b * T_LEN + t] * dilation;
        float tf = (float)t;
        int ip = __float2int_rn(tf - dil);   // round-half-even, matches jnp.round
        int iF = __float2int_rn(tf + dil);
        s_ip[tid] = (ip >= 0) ? ((ip < T_LEN) ? ip : (T_LEN - 1)) : -1;
        s_if[tid] = (iF < T_LEN) ? ((iF >= 0) ? iF : 0) : -1;
    }

    int oc0 = (tid & 63) * 4;    // 4 consecutive output channels
    int tb  = (tid >> 6) * 16;   // 16 consecutive time steps (8 f32x2 pairs)

    ull acc[4][8];
#pragma unroll
    for (int o = 0; o < 4; ++o)
#pragma unroll
        for (int p = 0; p < 8; ++p) acc[o][p] = 0ull;

    for (int c0 = 0; c0 < C_CH; c0 += CCHUNK) {
        __syncthreads();
        for (int j = tid; j < CCHUNK * TT; j += 256) {
            int c = j >> 6, tl = j & 63;
            const float* row = xb + (size_t)(c0 + c) * T_LEN;
            float v = row[t0 + tl];
            s_xt[j] = lrelu(v);
            int ip = s_ip[tl];
            s_xp[j] = (ip >= 0) ? lrelu(row[ip]) : 0.0f;
            int iF = s_if[tl];
            s_xf[j] = (iF >= 0) ? lrelu(row[iF]) : 0.0f;
        }
        __syncthreads();

#pragma unroll 1
        for (int c = 0; c < CCHUNK; ++c) {
            int wo = (c0 + c) * C_CH + oc0;
            float4 w0 = *(const float4*)(WtC + wo);
            float4 w1 = *(const float4*)(WtP + wo);
            float4 w2 = *(const float4*)(WtF + wo);
            ull wc[4] = {pack2(w0.x, w0.x), pack2(w0.y, w0.y), pack2(w0.z, w0.z), pack2(w0.w, w0.w)};
            ull wp[4] = {pack2(w1.x, w1.x), pack2(w1.y, w1.y), pack2(w1.z, w1.z), pack2(w1.w, w1.w)};
            ull wf[4] = {pack2(w2.x, w2.x), pack2(w2.y, w2.y), pack2(w2.z, w2.z), pack2(w2.w, w2.w)};
            int sb = c * TT + tb;
#pragma unroll
            for (int q = 0; q < 4; ++q) {
                longlong2 at = *(const longlong2*)(s_xt + sb + 4 * q);
                longlong2 ap = *(const longlong2*)(s_xp + sb + 4 * q);
                longlong2 af = *(const longlong2*)(s_xf + sb + 4 * q);
#pragma unroll
                for (int o = 0; o < 4; ++o) {
                    fma2(acc[o][2 * q],     (ull)at.x, wc[o]);
                    fma2(acc[o][2 * q + 1], (ull)at.y, wc[o]);
                    fma2(acc[o][2 * q],     (ull)ap.x, wp[o]);
                    fma2(acc[o][2 * q + 1], (ull)ap.y, wp[o]);
                    fma2(acc[o][2 * q],     (ull)af.x, wf[o]);
                    fma2(acc[o][2 * q + 1], (ull)af.y, wf[o]);
                }
            }
        }
    }

#pragma unroll
    for (int o = 0; o < 4; ++o) {
        float bs = bC[oc0 + o] + bP[oc0 + o] + bF[oc0 + o];
        float* yr = g_y + ((size_t)b * C_CH + oc0 + o) * T_LEN + t0 + tb;
#pragma unroll
        for (int p = 0; p < 8; ++p) {
            float2 v;
            v.x = lrelu(f_lo(acc[o][p]) + bs);
            v.y = lrelu(f_hi(acc[o][p]) + bs);
            *(float2*)(yr + 2 * p) = v;
        }
    }
}

// ---------------- stage 2: conv3 over g_y + residual (in-place on x) ----------------
__global__ __launch_bounds__(256, 2)
void k2_kernel(float* __restrict__ xio, int iter, const float* __restrict__ bA) {
    __shared__ float s_y[CCHUNK * 68];   // 64 rows x 66 valid cols (t0-1 .. t0+64), padded to 68

    const float* WtA = g_WtA + iter * 3 * 65536;

    int tid = threadIdx.x;
    int t0  = blockIdx.x * TT;
    int b   = blockIdx.y;

    int oc0 = (tid & 63) * 4;
    int tb  = (tid >> 6) * 16;

    ull acc[4][8];
#pragma unroll
    for (int o = 0; o < 4; ++o)
#pragma unroll
        for (int p = 0; p < 8; ++p) acc[o][p] = 0ull;

    for (int c0 = 0; c0 < C_CH; c0 += CCHUNK) {
        __syncthreads();
        for (int j = tid; j < CCHUNK * 66; j += 256) {
            int c = j / 66, jj = j % 66;
            int t = t0 - 1 + jj;
            float v = (t >= 0 && t < T_LEN)
                          ? g_y[((size_t)b * C_CH + c0 + c) * T_LEN + t]
                          : 0.0f;
            s_y[c * 68 + jj] = v;
        }
        __syncthreads();

#pragma unroll 1
        for (int c = 0; c < CCHUNK; ++c) {
            int wo = (c0 + c) * C_CH + oc0;
            float4 w0 = *(const float4*)(WtA + wo);            // tap k=0 (t-1)
            float4 w1 = *(const float4*)(WtA + 65536 + wo);    // tap k=1 (t)
            float4 w2 = *(const float4*)(WtA + 131072 + wo);   // tap k=2 (t+1)
            ull wk0[4] = {pack2(w0.x, w0.x), pack2(w0.y, w0.y), pack2(w0.z, w0.z), pack2(w0.w, w0.w)};
            ull wk1[4] = {pack2(w1.x, w1.x), pack2(w1.y, w1.y), pack2(w1.z, w1.z), pack2(w1.w, w1.w)};
            ull wk2[4] = {pack2(w2.x, w2.x), pack2(w2.y, w2.y), pack2(w2.z, w2.z), pack2(w2.w, w2.w)};

            const float* yr = s_y + c * 68 + tb;   // yr[j] = y[t0 - 1 + tb + j]
            ull L[9];
            longlong2 q0 = *(const longlong2*)(yr);      L[0] = (ull)q0.x; L[1] = (ull)q0.y;
            longlong2 q1 = *(const longlong2*)(yr + 4);  L[2] = (ull)q1.x; L[3] = (ull)q1.y;
            longlong2 q2 = *(const longlong2*)(yr + 8);  L[4] = (ull)q2.x; L[5] = (ull)q2.y;
            longlong2 q3 = *(const longlong2*)(yr + 12); L[6] = (ull)q3.x; L[7] = (ull)q3.y;
            L[8] = *(const ull*)(yr + 16);
#pragma unroll
            for (int p = 0; p < 8; ++p) {
                // L[p]   = (y[t-1], y[t])   for output pair starting at t = t0+tb+2p
                // L[p+1] = (y[t+1], y[t+2])
                ull mid = pack2(f_hi(L[p]), f_lo(L[p + 1]));   // (y[t], y[t+1])
#pragma unroll
                for (int o = 0; o < 4; ++o) {
                    fma2(acc[o][p], L[p],     wk0[o]);
                    fma2(acc[o][p], mid,      wk1[o]);
                    fma2(acc[o][p], L[p + 1], wk2[o]);
                }
            }
        }
    }

#pragma unroll
    for (int o = 0; o < 4; ++o) {
        float bs = bA[oc0 + o];
        float* xr = xio + ((size_t)b * C_CH + oc0 + o) * T_LEN + t0 + tb;
#pragma unroll
        for (int p = 0; p < 8; ++p) {
            float2 xv = *(float2*)(xr + 2 * p);
            float2 v;
            v.x = f_lo(acc[o][p]) + bs + xv.x;
            v.y = f_hi(acc[o][p]) + bs + xv.y;
            *(float2*)(xr + 2 * p) = v;
        }
    }
}

// ---------------- launch ----------------
extern "C" void kernel_launch(void* const* d_in, const int* in_sizes, int n_in,
                              void* d_out, int out_size) {
    const float* x  = (const float*)d_in[0];
    const float* d  = (const float*)d_in[1];
    const float* WC = (const float*)d_in[2];
    const float* bC = (const float*)d_in[3];
    const float* WP = (const float*)d_in[4];
    const float* bP = (const float*)d_in[5];
    const float* WF = (const float*)d_in[6];
    const float* bF = (const float*)d_in[7];
    const float* WA = (const float*)d_in[8];
    const float* bA = (const float*)d_in[9];
    float* xo = (float*)d_out;

    // running x lives in d_out; stage-1 output lives in g_y
    cudaMemcpyAsync(xo, x, (size_t)B_SZ * C_CH * T_LEN * sizeof(float),
                    cudaMemcpyDeviceToDevice);

    prep_kernel<<<768, 256>>>(WC, WP, WF, WA);

    int smem1 = (CCHUNK * TT * 3) * 4 + 2 * TT * 4;   // 49664 B
    cudaFuncSetAttribute((const void*)k1_kernel,
                         cudaFuncAttributeMaxDynamicSharedMemorySize, smem1);

    dim3 grid(T_LEN / TT, B_SZ);
    const float dils[3] = {1.0f, 2.0f, 4.0f};
    for (int i = 0; i < 3; ++i) {
        k1_kernel<<<grid, 256, smem1>>>(xo, d, bC + i * 256, bP + i * 256,
                                        bF + i * 256, i, dils[i]);
        k2_kernel<<<grid, 256>>>(xo, i, bA + i * 256);
    }
}

// round 3
// speedup vs baseline: 2.8367x; 2.8367x over previous
#include <cuda_runtime.h>
#include <cuda_bf16.h>

#define TL   8192
#define CC   256
#define BB   8
#define KTOT 768
#define KC   64
#define NCHK 12

typedef unsigned u32;
typedef unsigned short u16;

// ---------------- device scratch (bf16 planes) ----------------
__device__ u16 g_w1h[3*CC*KTOT], g_w1l[3*CC*KTOT];   // stage1 W [iter][oc][K]
__device__ u16 g_w2h[3*CC*KTOT], g_w2l[3*CC*KTOT];   // stage2 W
__device__ u16 g_xh[BB*TL*CC],   g_xl[BB*TL*CC];     // lrelu(x) split, [b][t][ch]
__device__ u16 g_yh[BB*TL*CC],   g_yl[BB*TL*CC];     // lrelu(stage1) split, [b][t][ch]

// ---------------- helpers ----------------
__device__ __forceinline__ u32 sm2u(const void* p) {
    u32 a;
    asm("{ .reg .u64 t; cvta.to.shared.u64 t, %1; cvt.u32.u64 %0, t; }" : "=r"(a) : "l"(p));
    return a;
}
__device__ __forceinline__ void cpa16(u32 s, const void* g, u32 sz) {
    asm volatile("cp.async.cg.shared.global [%0], [%1], 16, %2;" :: "r"(s), "l"(g), "r"(sz));
}
__device__ __forceinline__ void cpa_commit() { asm volatile("cp.async.commit_group;"); }
__device__ __forceinline__ void cpa_wait0()  { asm volatile("cp.async.wait_group 0;"); }

__device__ __forceinline__ void ldm4(u32 addr, u32* r) {
    asm volatile("ldmatrix.sync.aligned.m8n8.x4.shared.b16 {%0,%1,%2,%3}, [%4];"
                 : "=r"(r[0]), "=r"(r[1]), "=r"(r[2]), "=r"(r[3]) : "r"(addr));
}
__device__ __forceinline__ void mma16816(float* d, const u32* a, const u32* b) {
    asm volatile("mma.sync.aligned.m16n8k16.row.col.f32.bf16.bf16.f32 "
                 "{%0,%1,%2,%3}, {%4,%5,%6,%7}, {%8,%9}, {%0,%1,%2,%3};"
                 : "+f"(d[0]), "+f"(d[1]), "+f"(d[2]), "+f"(d[3])
                 : "r"(a[0]), "r"(a[1]), "r"(a[2]), "r"(a[3]), "r"(b[0]), "r"(b[1]));
}
__device__ __forceinline__ void split2(float v, u16& h, u16& l) {
    __nv_bfloat16 hb = __float2bfloat16_rn(v);
    float r = v - __bfloat162float(hb);
    h = __bfloat16_as_ushort(hb);
    l = __bfloat16_as_ushort(__float2bfloat16_rn(r));
}
__device__ __forceinline__ u32 pack_hl(float v) {
    u16 h, l; split2(v, h, l);
    return (u32)h | ((u32)l << 16);
}
__device__ __forceinline__ float lrelu(float v) { return fmaxf(v, 0.1f * v); }

// smem tile layout: [128 rows][8 x 16B units], unit swizzle u ^= (row & 7)
#define AH_OFF 0
#define AL_OFF 16384
#define BH_OFF 32768
#define BL_OFF 49152
#define BUFSZ  65536

// ---------------- prep: split all weights ----------------
__global__ void prep_w(const float* __restrict__ WC, const float* __restrict__ WP,
                       const float* __restrict__ WF, const float* __restrict__ WA) {
    int id = blockIdx.x * 256 + threadIdx.x;
    if (id >= 2 * 3 * CC * KTOT) return;
    int K = id % KTOT;
    int rest = id / KTOT;
    int oc = rest & 255;
    rest >>= 8;
    int i = rest % 3, stage = rest / 3;
    int sec = K >> 8, ch = K & 255;
    float w;
    if (stage == 0) {
        const float* W = (sec == 0) ? WC : (sec == 1) ? WP : WF;
        w = W[i * 65536 + oc * 256 + ch];
    } else {
        w = WA[(i * 65536 + oc * 256 + ch) * 3 + sec];
    }
    u16 h, l; split2(w, h, l);
    int dst = (i * CC + oc) * KTOT + K;
    if (stage == 0) { g_w1h[dst] = h; g_w1l[dst] = l; }
    else            { g_w2h[dst] = h; g_w2l[dst] = l; }
}

// ---------------- prex: lrelu + split + transpose x -> g_xh/g_xl [b][t][ch] ----------------
__global__ __launch_bounds__(256) void prex(const float* __restrict__ xo) {
    __shared__ u16 s_h[32 * 264], s_l[32 * 264];
    int b = blockIdx.y, t0 = blockIdx.x * 32;
    int tid = threadIdx.x;
    int chl = tid >> 3, tw = tid & 7;
    for (int cp = 0; cp < 8; ++cp) {
        int ch = cp * 32 + chl;
        const float4 v = *(const float4*)(xo + ((size_t)(b * 256 + ch)) * TL + t0 + tw * 4);
        float vv[4] = {v.x, v.y, v.z, v.w};
#pragma unroll
        for (int j = 0; j < 4; ++j) {
            u16 h, l; split2(lrelu(vv[j]), h, l);
            s_h[(tw * 4 + j) * 264 + ch] = h;
            s_l[(tw * 4 + j) * 264 + ch] = l;
        }
    }
    __syncthreads();
    u32* gh = (u32*)g_xh;
    u32* gl = (u32*)g_xl;
    const u32* sh = (const u32*)s_h;
    const u32* sl = (const u32*)s_l;
    for (int i = tid; i < 32 * 128; i += 256) {
        int t = i >> 7, j = i & 127;
        size_t o = ((size_t)(b * TL + t0 + t)) * 128 + j;
        gh[o] = sh[t * 132 + j];
        gl[o] = sl[t * 132 + j];
    }
}

// ---------------- chunk producers ----------------
__device__ __forceinline__ void issueA(u32 sbase, const u16* wh, const u16* wl,
                                       int kc, int mt, int tid) {
#pragma unroll
    for (int i = 0; i < 8; ++i) {
        int id = tid + i * 256;
        int plane = id >> 10, idx = id & 1023, r = idx >> 3, u = idx & 7;
        const u16* src = (plane ? wl : wh) + (size_t)(mt * 128 + r) * KTOT + kc * KC + u * 8;
        u32 dst = sbase + plane * 16384 + r * 128 + ((u ^ (r & 7)) << 4);
        cpa16(dst, src, 16);
    }
}
__device__ __forceinline__ void issueB(u32 sbase, const u16* xh, const u16* xl,
                                       int st_base_mode, int kc, int b, int t0,
                                       const int* s_ip, const int* s_if, int tid) {
    int sec = kc >> 2, ch0 = (kc & 3) << 6;
#pragma unroll
    for (int i = 0; i < 8; ++i) {
        int id = tid + i * 256;
        int plane = id >> 10, idx = id & 1023, r = idx >> 3, u = idx & 7;
        int st; u32 sz = 16;
        if (st_base_mode == 0) {  // k1: xt / xP / xF
            st = (sec == 0) ? (t0 + r) : ((sec == 1) ? s_ip[r] : s_if[r]);
            if (st < 0) { st = 0; sz = 0; }
        } else {                  // k2: conv3 taps
            st = t0 + r - 1 + sec;
            if (st < 0 || st >= TL) { st = 0; sz = 0; }
        }
        const u16* src = (plane ? xl : xh) + ((size_t)(b * TL + st)) * CC + ch0 + u * 8;
        u32 dst = sbase + BH_OFF + plane * 16384 + r * 128 + ((u ^ (r & 7)) << 4);
        cpa16(dst, src, sz);
    }
}

// ---------------- MMA core ----------------
struct Frag { float acc[4][4][4]; };

__device__ __forceinline__ void compute_chunk(u32 base, const int* aoff, const int* asw,
                                              const int* boff, const int* bsw,
                                              int lsel, int ubsel, float acc[4][4][4]) {
#pragma unroll
    for (int s = 0; s < 4; ++s) {
        u32 ah[4][4], al[4][4], bh[2][4], bl[2][4];
#pragma unroll
        for (int mf = 0; mf < 4; ++mf) {
            u32 ua = (u32)(((2 * s + lsel) ^ asw[mf]) << 4);
            ldm4(base + AH_OFF + aoff[mf] + ua, ah[mf]);
            ldm4(base + AL_OFF + aoff[mf] + ua, al[mf]);
        }
#pragma unroll
        for (int nf = 0; nf < 2; ++nf) {
            u32 ub = (u32)(((2 * s + ubsel) ^ bsw[nf]) << 4);
            ldm4(base + BH_OFF + boff[nf] + ub, bh[nf]);
            ldm4(base + BL_OFF + boff[nf] + ub, bl[nf]);
        }
#pragma unroll
        for (int mf = 0; mf < 4; ++mf)
#pragma unroll
            for (int nb = 0; nb < 4; ++nb) {
                const u32* bhf = &bh[nb >> 1][(nb & 1) * 2];
                const u32* blf = &bl[nb >> 1][(nb & 1) * 2];
                mma16816(acc[mf][nb], ah[mf], bhf);
                mma16816(acc[mf][nb], ah[mf], blf);
                mma16816(acc[mf][nb], al[mf], bhf);
            }
    }
}

// ---------------- stage 1 GEMM kernel ----------------
__global__ __launch_bounds__(256, 1)
void k1(const float* __restrict__ dfac, const float* __restrict__ bC,
        const float* __restrict__ bP, const float* __restrict__ bF,
        int iter, float dilation) {
    extern __shared__ __align__(1024) unsigned char dynsm[];
    __shared__ int s_ip[128], s_if[128];

    const int tid = threadIdx.x, wid = tid >> 5, lid = tid & 31;
    const int wm = wid & 1, wn = wid >> 1;
    const int b = blockIdx.z, mt = blockIdx.y, t0 = blockIdx.x * 128;
    const u32 sb = sm2u(dynsm);

    if (tid < 128) {
        int t = t0 + tid;
        float dil = dfac[b * TL + t] * dilation;
        int ip = __float2int_rn((float)t - dil);
        int iF = __float2int_rn((float)t + dil);
        s_ip[tid] = (ip >= 0) ? ip : -1;
        s_if[tid] = (iF < TL) ? iF : -1;
    }
    __syncthreads();

    const u16* wh = g_w1h + (size_t)iter * CC * KTOT;
    const u16* wl = g_w1l + (size_t)iter * CC * KTOT;

    int aoff[4], asw[4], boff[2], bsw[2];
    int lsel = lid >> 4, ubsel = (lid >> 3) & 1;
#pragma unroll
    for (int mf = 0; mf < 4; ++mf) {
        int r = wm * 64 + mf * 16 + (lid & 15);
        aoff[mf] = r * 128; asw[mf] = r & 7;
    }
#pragma unroll
    for (int nf = 0; nf < 2; ++nf) {
        int r = wn * 32 + nf * 16 + (lid & 7) + 8 * (lid >> 4);
        boff[nf] = r * 128; bsw[nf] = r & 7;
    }

    float acc[4][4][4];
#pragma unroll
    for (int a = 0; a < 4; ++a)
#pragma unroll
        for (int c = 0; c < 4; ++c)
#pragma unroll
            for (int d = 0; d < 4; ++d) acc[a][c][d] = 0.f;

    issueA(sb, wh, wl, 0, mt, tid);
    issueB(sb, g_xh + (size_t)0, g_xl + (size_t)0, 0, 0, b, t0, s_ip, s_if, tid);
    cpa_commit();
    for (int kc = 0; kc < NCHK; ++kc) {
        cpa_wait0();
        __syncthreads();
        if (kc + 1 < NCHK) {
            u32 nb = sb + ((kc + 1) & 1) * BUFSZ;
            issueA(nb, wh, wl, kc + 1, mt, tid);
            issueB(nb, g_xh, g_xl, 0, kc + 1, b, t0, s_ip, s_if, tid);
            cpa_commit();
        }
        compute_chunk(sb + (kc & 1) * BUFSZ, aoff, asw, boff, bsw, lsel, ubsel, acc);
    }

    // epilogue: bias + lrelu + split, transpose via smem, store [t][ch] planes
    __syncthreads();
    u32* ep = (u32*)dynsm;   // [128 cols(t)][132 rows(oc)]
    int gq = lid >> 2, cq = 2 * (lid & 3);
#pragma unroll
    for (int mf = 0; mf < 4; ++mf) {
        int r0 = wm * 64 + mf * 16 + gq, r1 = r0 + 8;
        int g0 = mt * 128 + r0, g1 = mt * 128 + r1;
        float bs0 = bC[g0] + bP[g0] + bF[g0];
        float bs1 = bC[g1] + bP[g1] + bF[g1];
#pragma unroll
        for (int nb = 0; nb < 4; ++nb) {
            int c = wn * 32 + nb * 8 + cq;
            const float* a = acc[mf][nb];
            ep[c * 132 + r0]       = pack_hl(lrelu(a[0] + bs0));
            ep[(c + 1) * 132 + r0] = pack_hl(lrelu(a[1] + bs0));
            ep[c * 132 + r1]       = pack_hl(lrelu(a[2] + bs1));
            ep[(c + 1) * 132 + r1] = pack_hl(lrelu(a[3] + bs1));
        }
    }
    __syncthreads();
    u32* yh = (u32*)g_yh;
    u32* yl = (u32*)g_yl;
    for (int i = tid; i < 128 * 64; i += 256) {
        int t = i >> 6, j = i & 63;
        u32 p0 = ep[t * 132 + 2 * j], p1 = ep[t * 132 + 2 * j + 1];
        size_t o = ((size_t)(b * TL + t0 + t)) * 128 + mt * 64 + j;
        yh[o] = (p0 & 0xFFFFu) | (p1 << 16);
        yl[o] = (p0 >> 16) | (p1 & 0xFFFF0000u);
    }
}

// ---------------- stage 2 GEMM kernel (conv3 + residual) ----------------
__global__ __launch_bounds__(256, 1)
void k2(float* __restrict__ xo, const float* __restrict__ bA, int iter) {
    extern __shared__ __align__(1024) unsigned char dynsm[];

    const int tid = threadIdx.x, wid = tid >> 5, lid = tid & 31;
    const int wm = wid & 1, wn = wid >> 1;
    const int b = blockIdx.z, mt = blockIdx.y, t0 = blockIdx.x * 128;
    const u32 sb = sm2u(dynsm);

    const u16* wh = g_w2h + (size_t)iter * CC * KTOT;
    const u16* wl = g_w2l + (size_t)iter * CC * KTOT;

    int aoff[4], asw[4], boff[2], bsw[2];
    int lsel = lid >> 4, ubsel = (lid >> 3) & 1;
#pragma unroll
    for (int mf = 0; mf < 4; ++mf) {
        int r = wm * 64 + mf * 16 + (lid & 15);
        aoff[mf] = r * 128; asw[mf] = r & 7;
    }
#pragma unroll
    for (int nf = 0; nf < 2; ++nf) {
        int r = wn * 32 + nf * 16 + (lid & 7) + 8 * (lid >> 4);
        boff[nf] = r * 128; bsw[nf] = r & 7;
    }

    float acc[4][4][4];
#pragma unroll
    for (int a = 0; a < 4; ++a)
#pragma unroll
        for (int c = 0; c < 4; ++c)
#pragma unroll
            for (int d = 0; d < 4; ++d) acc[a][c][d] = 0.f;

    issueA(sb, wh, wl, 0, mt, tid);
    issueB(sb, g_yh, g_yl, 1, 0, b, t0, 0, 0, tid);
    cpa_commit();
    for (int kc = 0; kc < NCHK; ++kc) {
        cpa_wait0();
        __syncthreads();
        if (kc + 1 < NCHK) {
            u32 nb = sb + ((kc + 1) & 1) * BUFSZ;
            issueA(nb, wh, wl, kc + 1, mt, tid);
            issueB(nb, g_yh, g_yl, 1, kc + 1, b, t0, 0, 0, tid);
            cpa_commit();
        }
        compute_chunk(sb + (kc & 1) * BUFSZ, aoff, asw, boff, bsw, lsel, ubsel, acc);
    }

    // epilogue: bias + residual, coalesced float2 RMW on xo
    int gq = lid >> 2, cq = 2 * (lid & 3);
#pragma unroll
    for (int mf = 0; mf < 4; ++mf) {
        int r0 = wm * 64 + mf * 16 + gq, r1 = r0 + 8;
        int g0 = mt * 128 + r0, g1 = mt * 128 + r1;
        float bs0 = bA[g0], bs1 = bA[g1];
        float* p0b = xo + ((size_t)(b * CC + g0)) * TL + t0;
        float* p1b = xo + ((size_t)(b * CC + g1)) * TL + t0;
#pragma unroll
        for (int nb = 0; nb < 4; ++nb) {
            int c = wn * 32 + nb * 8 + cq;
            const float* a = acc[mf][nb];
            float2* q0 = (float2*)(p0b + c);
            float2 v0 = *q0;
            v0.x += a[0] + bs0; v0.y += a[1] + bs0;
            *q0 = v0;
            float2* q1 = (float2*)(p1b + c);
            float2 v1 = *q1;
            v1.x += a[2] + bs1; v1.y += a[3] + bs1;
            *q1 = v1;
        }
    }
}

// ---------------- launch ----------------
extern "C" void kernel_launch(void* const* d_in, const int* in_sizes, int n_in,
                              void* d_out, int out_size) {
    const float* x  = (const float*)d_in[0];
    const float* d  = (const float*)d_in[1];
    const float* WC = (const float*)d_in[2];
    const float* bC = (const float*)d_in[3];
    const float* WP = (const float*)d_in[4];
    const float* bP = (const float*)d_in[5];
    const float* WF = (const float*)d_in[6];
    const float* bF = (const float*)d_in[7];
    const float* WA = (const float*)d_in[8];
    const float* bA = (const float*)d_in[9];
    float* xo = (float*)d_out;

    cudaMemcpyAsync(xo, x, (size_t)BB * CC * TL * sizeof(float),
                    cudaMemcpyDeviceToDevice);

    prep_w<<<(2 * 3 * CC * KTOT + 255) / 256, 256>>>(WC, WP, WF, WA);

    const int DSMEM = 2 * BUFSZ;   // 128 KB
    cudaFuncSetAttribute((const void*)k1, cudaFuncAttributeMaxDynamicSharedMemorySize, DSMEM);
    cudaFuncSetAttribute((const void*)k2, cudaFuncAttributeMaxDynamicSharedMemorySize, DSMEM);

    dim3 gprex(TL / 32, BB);
    dim3 grid(TL / 128, 2, BB);
    const float dils[3] = {1.0f, 2.0f, 4.0f};
    for (int i = 0; i < 3; ++i) {
        prex<<<gprex, 256>>>(xo);
        k1<<<grid, 256, DSMEM>>>(d, bC + i * 256, bP + i * 256, bF + i * 256, i, dils[i]);
        k2<<<grid, 256, DSMEM>>>(xo, bA + i * 256, i);
    }
}

// round 4
// speedup vs baseline: 3.0473x; 1.0742x over previous
#include <cuda_runtime.h>
#include <cuda_bf16.h>

#define TL   8192
#define CC   256
#define BB   8
#define KTOT 768
#define KC   64
#define NCHK 12
#define NTHR 512

typedef unsigned u32;
typedef unsigned short u16;

// ---------------- device scratch (bf16 planes) ----------------
__device__ u16 g_w1h[3*CC*KTOT], g_w1l[3*CC*KTOT];   // stage1 W [iter][oc][K]
__device__ u16 g_w2h[3*CC*KTOT], g_w2l[3*CC*KTOT];   // stage2 W
__device__ u16 g_xh[BB*TL*CC],   g_xl[BB*TL*CC];     // lrelu(x) split, [b][t][ch]
__device__ u16 g_yh[BB*TL*CC],   g_yl[BB*TL*CC];     // lrelu(stage1) split, [b][t][ch]

// ---------------- helpers ----------------
__device__ __forceinline__ u32 sm2u(const void* p) {
    u32 a;
    asm("{ .reg .u64 t; cvta.to.shared.u64 t, %1; cvt.u32.u64 %0, t; }" : "=r"(a) : "l"(p));
    return a;
}
__device__ __forceinline__ void cpa16(u32 s, const void* g, u32 sz) {
    asm volatile("cp.async.cg.shared.global [%0], [%1], 16, %2;" :: "r"(s), "l"(g), "r"(sz));
}
__device__ __forceinline__ void cpa_commit() { asm volatile("cp.async.commit_group;"); }
__device__ __forceinline__ void cpa_wait0()  { asm volatile("cp.async.wait_group 0;"); }

__device__ __forceinline__ void ldm4(u32 addr, u32* r) {
    asm volatile("ldmatrix.sync.aligned.m8n8.x4.shared.b16 {%0,%1,%2,%3}, [%4];"
                 : "=r"(r[0]), "=r"(r[1]), "=r"(r[2]), "=r"(r[3]) : "r"(addr));
}
__device__ __forceinline__ void mma16816(float* d, const u32* a, const u32* b) {
    asm volatile("mma.sync.aligned.m16n8k16.row.col.f32.bf16.bf16.f32 "
                 "{%0,%1,%2,%3}, {%4,%5,%6,%7}, {%8,%9}, {%0,%1,%2,%3};"
                 : "+f"(d[0]), "+f"(d[1]), "+f"(d[2]), "+f"(d[3])
                 : "r"(a[0]), "r"(a[1]), "r"(a[2]), "r"(a[3]), "r"(b[0]), "r"(b[1]));
}
__device__ __forceinline__ void split2(float v, u16& h, u16& l) {
    __nv_bfloat16 hb = __float2bfloat16_rn(v);
    float r = v - __bfloat162float(hb);
    h = __bfloat16_as_ushort(hb);
    l = __bfloat16_as_ushort(__float2bfloat16_rn(r));
}
__device__ __forceinline__ u32 pack_hl(float v) {
    u16 h, l; split2(v, h, l);
    return (u32)h | ((u32)l << 16);
}
__device__ __forceinline__ float lrelu(float v) { return fmaxf(v, 0.1f * v); }

// smem tile layout: [128 rows][8 x 16B units], unit swizzle u ^= (row & 7)
#define AH_OFF 0
#define AL_OFF 16384
#define BH_OFF 32768
#define BL_OFF 49152
#define BUFSZ  65536

// ---------------- prep: split all weights ----------------
__global__ void prep_w(const float* __restrict__ WC, const float* __restrict__ WP,
                       const float* __restrict__ WF, const float* __restrict__ WA) {
    int id = blockIdx.x * 256 + threadIdx.x;
    if (id >= 2 * 3 * CC * KTOT) return;
    int K = id % KTOT;
    int rest = id / KTOT;
    int oc = rest & 255;
    rest >>= 8;
    int i = rest % 3, stage = rest / 3;
    int sec = K >> 8, ch = K & 255;
    float w;
    if (stage == 0) {
        const float* W = (sec == 0) ? WC : (sec == 1) ? WP : WF;
        w = W[i * 65536 + oc * 256 + ch];
    } else {
        w = WA[(i * 65536 + oc * 256 + ch) * 3 + sec];
    }
    u16 h, l; split2(w, h, l);
    int dst = (i * CC + oc) * KTOT + K;
    if (stage == 0) { g_w1h[dst] = h; g_w1l[dst] = l; }
    else            { g_w2h[dst] = h; g_w2l[dst] = l; }
}

// ---------------- prex: lrelu + split + transpose x -> g_xh/g_xl [b][t][ch] ----------------
__global__ __launch_bounds__(256) void prex(const float* __restrict__ xo) {
    __shared__ u16 s_h[32 * 264], s_l[32 * 264];
    int b = blockIdx.y, t0 = blockIdx.x * 32;
    int tid = threadIdx.x;
    int chl = tid >> 3, tw = tid & 7;
    for (int cp = 0; cp < 8; ++cp) {
        int ch = cp * 32 + chl;
        const float4 v = *(const float4*)(xo + ((size_t)(b * 256 + ch)) * TL + t0 + tw * 4);
        float vv[4] = {v.x, v.y, v.z, v.w};
#pragma unroll
        for (int j = 0; j < 4; ++j) {
            u16 h, l; split2(lrelu(vv[j]), h, l);
            s_h[(tw * 4 + j) * 264 + ch] = h;
            s_l[(tw * 4 + j) * 264 + ch] = l;
        }
    }
    __syncthreads();
    u32* gh = (u32*)g_xh;
    u32* gl = (u32*)g_xl;
    const u32* sh = (const u32*)s_h;
    const u32* sl = (const u32*)s_l;
    for (int i = tid; i < 32 * 128; i += 256) {
        int t = i >> 7, j = i & 127;
        size_t o = ((size_t)(b * TL + t0 + t)) * 128 + j;
        gh[o] = sh[t * 132 + j];
        gl[o] = sl[t * 132 + j];
    }
}

// ---------------- chunk producers (512 threads) ----------------
__device__ __forceinline__ void issueA(u32 sbase, const u16* wh, const u16* wl,
                                       int kc, int mt, int tid) {
#pragma unroll
    for (int i = 0; i < 4; ++i) {
        int id = tid + i * NTHR;
        int plane = id >> 10, idx = id & 1023, r = idx >> 3, u = idx & 7;
        const u16* src = (plane ? wl : wh) + (size_t)(mt * 128 + r) * KTOT + kc * KC + u * 8;
        u32 dst = sbase + plane * 16384 + r * 128 + ((u ^ (r & 7)) << 4);
        cpa16(dst, src, 16);
    }
}
__device__ __forceinline__ void issueB(u32 sbase, const u16* xh, const u16* xl,
                                       int st_base_mode, int kc, int b, int t0,
                                       const int* s_ip, const int* s_if, int tid) {
    int sec = kc >> 2, ch0 = (kc & 3) << 6;
#pragma unroll
    for (int i = 0; i < 4; ++i) {
        int id = tid + i * NTHR;
        int plane = id >> 10, idx = id & 1023, r = idx >> 3, u = idx & 7;
        int st; u32 sz = 16;
        if (st_base_mode == 0) {  // k1: xt / xP / xF
            st = (sec == 0) ? (t0 + r) : ((sec == 1) ? s_ip[r] : s_if[r]);
            if (st < 0) { st = 0; sz = 0; }
        } else {                  // k2: conv3 taps
            st = t0 + r - 1 + sec;
            if (st < 0 || st >= TL) { st = 0; sz = 0; }
        }
        const u16* src = (plane ? xl : xh) + ((size_t)(b * TL + st)) * CC + ch0 + u * 8;
        u32 dst = sbase + BH_OFF + plane * 16384 + r * 128 + ((u ^ (r & 7)) << 4);
        cpa16(dst, src, sz);
    }
}

// ---------------- MMA core: warp tile 32x32, 16 warps ----------------
__device__ __forceinline__ void compute_chunk(u32 base, const int* aoff, const int* asw,
                                              const int* boff, const int* bsw,
                                              int lsel, int ubsel, float acc[2][4][4]) {
#pragma unroll
    for (int s = 0; s < 4; ++s) {
        u32 ah[2][4], al[2][4], bh[2][4], bl[2][4];
#pragma unroll
        for (int mf = 0; mf < 2; ++mf) {
            u32 ua = (u32)(((2 * s + lsel) ^ asw[mf]) << 4);
            ldm4(base + AH_OFF + aoff[mf] + ua, ah[mf]);
            ldm4(base + AL_OFF + aoff[mf] + ua, al[mf]);
        }
#pragma unroll
        for (int nf = 0; nf < 2; ++nf) {
            u32 ub = (u32)(((2 * s + ubsel) ^ bsw[nf]) << 4);
            ldm4(base + BH_OFF + boff[nf] + ub, bh[nf]);
            ldm4(base + BL_OFF + boff[nf] + ub, bl[nf]);
        }
#pragma unroll
        for (int mf = 0; mf < 2; ++mf)
#pragma unroll
            for (int nb = 0; nb < 4; ++nb) {
                const u32* bhf = &bh[nb >> 1][(nb & 1) * 2];
                const u32* blf = &bl[nb >> 1][(nb & 1) * 2];
                mma16816(acc[mf][nb], ah[mf], bhf);
                mma16816(acc[mf][nb], ah[mf], blf);
                mma16816(acc[mf][nb], al[mf], bhf);
            }
    }
}

// fragment address setup (shared by k1/k2)
__device__ __forceinline__ void frag_setup(int wm, int wn, int lid,
                                           int* aoff, int* asw, int* boff, int* bsw) {
#pragma unroll
    for (int mf = 0; mf < 2; ++mf) {
        int r = wm * 32 + mf * 16 + (lid & 15);
        aoff[mf] = r * 128; asw[mf] = r & 7;
    }
#pragma unroll
    for (int nf = 0; nf < 2; ++nf) {
        int r = wn * 32 + nf * 16 + (lid & 7) + 8 * (lid >> 4);
        boff[nf] = r * 128; bsw[nf] = r & 7;
    }
}

// ---------------- stage 1 GEMM kernel ----------------
__global__ __launch_bounds__(NTHR, 1)
void k1(const float* __restrict__ dfac, const float* __restrict__ bC,
        const float* __restrict__ bP, const float* __restrict__ bF,
        int iter, float dilation) {
    extern __shared__ __align__(1024) unsigned char dynsm[];
    __shared__ int s_ip[128], s_if[128];

    const int tid = threadIdx.x, wid = tid >> 5, lid = tid & 31;
    const int wm = wid & 3, wn = wid >> 2;
    const int b = blockIdx.z, mt = blockIdx.y, t0 = blockIdx.x * 128;
    const u32 sb = sm2u(dynsm);

    if (tid < 128) {
        int t = t0 + tid;
        float dil = dfac[b * TL + t] * dilation;
        int ip = __float2int_rn((float)t - dil);
        int iF = __float2int_rn((float)t + dil);
        s_ip[tid] = (ip >= 0) ? ip : -1;
        s_if[tid] = (iF < TL) ? iF : -1;
    }
    __syncthreads();

    const u16* wh = g_w1h + (size_t)iter * CC * KTOT;
    const u16* wl = g_w1l + (size_t)iter * CC * KTOT;

    int aoff[2], asw[2], boff[2], bsw[2];
    int lsel = lid >> 4, ubsel = (lid >> 3) & 1;
    frag_setup(wm, wn, lid, aoff, asw, boff, bsw);

    float acc[2][4][4];
#pragma unroll
    for (int a = 0; a < 2; ++a)
#pragma unroll
        for (int c = 0; c < 4; ++c)
#pragma unroll
            for (int d = 0; d < 4; ++d) acc[a][c][d] = 0.f;

    issueA(sb, wh, wl, 0, mt, tid);
    issueB(sb, g_xh, g_xl, 0, 0, b, t0, s_ip, s_if, tid);
    cpa_commit();
    for (int kc = 0; kc < NCHK; ++kc) {
        cpa_wait0();
        __syncthreads();
        if (kc + 1 < NCHK) {
            u32 nb = sb + ((kc + 1) & 1) * BUFSZ;
            issueA(nb, wh, wl, kc + 1, mt, tid);
            issueB(nb, g_xh, g_xl, 0, kc + 1, b, t0, s_ip, s_if, tid);
            cpa_commit();
        }
        compute_chunk(sb + (kc & 1) * BUFSZ, aoff, asw, boff, bsw, lsel, ubsel, acc);
    }

    // epilogue: bias + lrelu + split, transpose via smem, store [t][ch] planes
    __syncthreads();
    u32* ep = (u32*)dynsm;   // [128 cols(t)][132 rows(oc)]
    int gq = lid >> 2, cq = 2 * (lid & 3);
#pragma unroll
    for (int mf = 0; mf < 2; ++mf) {
        int r0 = wm * 32 + mf * 16 + gq, r1 = r0 + 8;
        int g0 = mt * 128 + r0, g1 = mt * 128 + r1;
        float bs0 = bC[g0] + bP[g0] + bF[g0];
        float bs1 = bC[g1] + bP[g1] + bF[g1];
#pragma unroll
        for (int nb = 0; nb < 4; ++nb) {
            int c = wn * 32 + nb * 8 + cq;
            const float* a = acc[mf][nb];
            ep[c * 132 + r0]       = pack_hl(lrelu(a[0] + bs0));
            ep[(c + 1) * 132 + r0] = pack_hl(lrelu(a[1] + bs0));
            ep[c * 132 + r1]       = pack_hl(lrelu(a[2] + bs1));
            ep[(c + 1) * 132 + r1] = pack_hl(lrelu(a[3] + bs1));
        }
    }
    __syncthreads();
    u32* yh = (u32*)g_yh;
    u32* yl = (u32*)g_yl;
    for (int i = tid; i < 128 * 64; i += NTHR) {
        int t = i >> 6, j = i & 63;
        u32 p0 = ep[t * 132 + 2 * j], p1 = ep[t * 132 + 2 * j + 1];
        size_t o = ((size_t)(b * TL + t0 + t)) * 128 + mt * 64 + j;
        yh[o] = (p0 & 0xFFFFu) | (p1 << 16);
        yl[o] = (p0 >> 16) | (p1 & 0xFFFF0000u);
    }
}

// ---------------- stage 2 GEMM kernel (conv3 + residual) ----------------
__global__ __launch_bounds__(NTHR, 1)
void k2(float* __restrict__ xo, const float* __restrict__ bA, int iter) {
    extern __shared__ __align__(1024) unsigned char dynsm[];

    const int tid = threadIdx.x, wid = tid >> 5, lid = tid & 31;
    const int wm = wid & 3, wn = wid >> 2;
    const int b = blockIdx.z, mt = blockIdx.y, t0 = blockIdx.x * 128;
    const u32 sb = sm2u(dynsm);

    const u16* wh = g_w2h + (size_t)iter * CC * KTOT;
    const u16* wl = g_w2l + (size_t)iter * CC * KTOT;

    int aoff[2], asw[2], boff[2], bsw[2];
    int lsel = lid >> 4, ubsel = (lid >> 3) & 1;
    frag_setup(wm, wn, lid, aoff, asw, boff, bsw);

    float acc[2][4][4];
#pragma unroll
    for (int a = 0; a < 2; ++a)
#pragma unroll
        for (int c = 0; c < 4; ++c)
#pragma unroll
            for (int d = 0; d < 4; ++d) acc[a][c][d] = 0.f;

    issueA(sb, wh, wl, 0, mt, tid);
    issueB(sb, g_yh, g_yl, 1, 0, b, t0, 0, 0, tid);
    cpa_commit();
    for (int kc = 0; kc < NCHK; ++kc) {
        cpa_wait0();
        __syncthreads();
        if (kc + 1 < NCHK) {
            u32 nb = sb + ((kc + 1) & 1) * BUFSZ;
            issueA(nb, wh, wl, kc + 1, mt, tid);
            issueB(nb, g_yh, g_yl, 1, kc + 1, b, t0, 0, 0, tid);
            cpa_commit();
        }
        compute_chunk(sb + (kc & 1) * BUFSZ, aoff, asw, boff, bsw, lsel, ubsel, acc);
    }

    // epilogue: bias + residual, coalesced float2 RMW on xo
    int gq = lid >> 2, cq = 2 * (lid & 3);
#pragma unroll
    for (int mf = 0; mf < 2; ++mf) {
        int r0 = wm * 32 + mf * 16 + gq, r1 = r0 + 8;
        int g0 = mt * 128 + r0, g1 = mt * 128 + r1;
        float bs0 = bA[g0], bs1 = bA[g1];
        float* p0b = xo + ((size_t)(b * CC + g0)) * TL + t0;
        float* p1b = xo + ((size_t)(b * CC + g1)) * TL + t0;
#pragma unroll
        for (int nb = 0; nb < 4; ++nb) {
            int c = wn * 32 + nb * 8 + cq;
            const float* a = acc[mf][nb];
            float2* q0 = (float2*)(p0b + c);
            float2 v0 = *q0;
            v0.x += a[0] + bs0; v0.y += a[1] + bs0;
            *q0 = v0;
            float2* q1 = (float2*)(p1b + c);
            float2 v1 = *q1;
            v1.x += a[2] + bs1; v1.y += a[3] + bs1;
            *q1 = v1;
        }
    }
}

// ---------------- launch ----------------
extern "C" void kernel_launch(void* const* d_in, const int* in_sizes, int n_in,
                              void* d_out, int out_size) {
    const float* x  = (const float*)d_in[0];
    const float* d  = (const float*)d_in[1];
    const float* WC = (const float*)d_in[2];
    const float* bC = (const float*)d_in[3];
    const float* WP = (const float*)d_in[4];
    const float* bP = (const float*)d_in[5];
    const float* WF = (const float*)d_in[6];
    const float* bF = (const float*)d_in[7];
    const float* WA = (const float*)d_in[8];
    const float* bA = (const float*)d_in[9];
    float* xo = (float*)d_out;

    cudaMemcpyAsync(xo, x, (size_t)BB * CC * TL * sizeof(float),
                    cudaMemcpyDeviceToDevice);

    prep_w<<<(2 * 3 * CC * KTOT + 255) / 256, 256>>>(WC, WP, WF, WA);

    const int DSMEM = 2 * BUFSZ;   // 128 KB
    cudaFuncSetAttribute((const void*)k1, cudaFuncAttributeMaxDynamicSharedMemorySize, DSMEM);
    cudaFuncSetAttribute((const void*)k2, cudaFuncAttributeMaxDynamicSharedMemorySize, DSMEM);

    dim3 gprex(TL / 32, BB);
    dim3 grid(TL / 128, 2, BB);
    const float dils[3] = {1.0f, 2.0f, 4.0f};
    for (int i = 0; i < 3; ++i) {
        prex<<<gprex, 256>>>(xo);
        k1<<<grid, NTHR, DSMEM>>>(d, bC + i * 256, bP + i * 256, bF + i * 256, i, dils[i]);
        k2<<<grid, NTHR, DSMEM>>>(xo, bA + i * 256, i);
    }
}

// round 5
// speedup vs baseline: 4.1751x; 1.3701x over previous
#include <cuda_runtime.h>
#include <cuda_fp16.h>

#define TL   8192
#define CC   256
#define BB   8
#define KTOT 768
#define KC   64
#define NCHK 12
#define NTHR 512

typedef unsigned u32;
typedef unsigned short u16;

// ---------------- device scratch (fp16 planes) ----------------
__device__ u16 g_w1h[3*CC*KTOT], g_w1l[3*CC*KTOT];   // stage1 W split [iter][oc][K]
__device__ u16 g_w2h[3*CC*KTOT], g_w2l[3*CC*KTOT];   // stage2 W split
__device__ u16 g_xh[BB*TL*CC];                        // fp16(lrelu(x)), [b][t][ch]
__device__ u16 g_yh[BB*TL*CC];                        // fp16(lrelu(stage1 out))

// ---------------- helpers ----------------
__device__ __forceinline__ u32 sm2u(const void* p) {
    u32 a;
    asm("{ .reg .u64 t; cvta.to.shared.u64 t, %1; cvt.u32.u64 %0, t; }" : "=r"(a) : "l"(p));
    return a;
}
__device__ __forceinline__ void cpa16(u32 s, const void* g, u32 sz) {
    asm volatile("cp.async.cg.shared.global [%0], [%1], 16, %2;" :: "r"(s), "l"(g), "r"(sz));
}
__device__ __forceinline__ void cpa_commit() { asm volatile("cp.async.commit_group;"); }
__device__ __forceinline__ void cpa_wait0()  { asm volatile("cp.async.wait_group 0;"); }
__device__ __forceinline__ void cpa_wait1()  { asm volatile("cp.async.wait_group 1;"); }

__device__ __forceinline__ void ldm4(u32 addr, u32* r) {
    asm volatile("ldmatrix.sync.aligned.m8n8.x4.shared.b16 {%0,%1,%2,%3}, [%4];"
                 : "=r"(r[0]), "=r"(r[1]), "=r"(r[2]), "=r"(r[3]) : "r"(addr));
}
__device__ __forceinline__ void mma16816(float* d, const u32* a, const u32* b) {
    asm volatile("mma.sync.aligned.m16n8k16.row.col.f32.f16.f16.f32 "
                 "{%0,%1,%2,%3}, {%4,%5,%6,%7}, {%8,%9}, {%0,%1,%2,%3};"
                 : "+f"(d[0]), "+f"(d[1]), "+f"(d[2]), "+f"(d[3])
                 : "r"(a[0]), "r"(a[1]), "r"(a[2]), "r"(a[3]), "r"(b[0]), "r"(b[1]));
}
__device__ __forceinline__ void split2h(float v, u16& h, u16& l) {
    __half hb = __float2half_rn(v);
    float r = v - __half2float(hb);
    h = __half_as_ushort(hb);
    l = __half_as_ushort(__float2half_rn(r));
}
__device__ __forceinline__ u16 h16(float v) { return __half_as_ushort(__float2half_rn(v)); }
__device__ __forceinline__ float lrelu(float v) { return fmaxf(v, 0.1f * v); }

// smem tile layout: [128 rows][8 x 16B units], unit swizzle u ^= (row & 7)
#define AH_OFF 0
#define AL_OFF 16384
#define BH_OFF 32768
#define BUFSZ  49152    // Ah 16K + Al 16K + Bh 16K

// ---------------- prep: split all weights into fp16 h/l ----------------
__global__ void prep_w(const float* __restrict__ WC, const float* __restrict__ WP,
                       const float* __restrict__ WF, const float* __restrict__ WA) {
    int id = blockIdx.x * 256 + threadIdx.x;
    if (id >= 2 * 3 * CC * KTOT) return;
    int K = id % KTOT;
    int rest = id / KTOT;
    int oc = rest & 255;
    rest >>= 8;
    int i = rest % 3, stage = rest / 3;
    int sec = K >> 8, ch = K & 255;
    float w;
    if (stage == 0) {
        const float* W = (sec == 0) ? WC : (sec == 1) ? WP : WF;
        w = W[i * 65536 + oc * 256 + ch];
    } else {
        w = WA[(i * 65536 + oc * 256 + ch) * 3 + sec];
    }
    u16 h, l; split2h(w, h, l);
    int dst = (i * CC + oc) * KTOT + K;
    if (stage == 0) { g_w1h[dst] = h; g_w1l[dst] = l; }
    else            { g_w2h[dst] = h; g_w2l[dst] = l; }
}

// ---------------- prex: lrelu + fp16 + transpose x -> g_xh [b][t][ch] (iter 0 only) ----------------
__global__ __launch_bounds__(256) void prex(const float* __restrict__ xo) {
    __shared__ u16 s_h[32 * 264];
    int b = blockIdx.y, t0 = blockIdx.x * 32;
    int tid = threadIdx.x;
    int chl = tid >> 3, tw = tid & 7;
    for (int cp = 0; cp < 8; ++cp) {
        int ch = cp * 32 + chl;
        const float4 v = *(const float4*)(xo + ((size_t)(b * 256 + ch)) * TL + t0 + tw * 4);
        float vv[4] = {v.x, v.y, v.z, v.w};
#pragma unroll
        for (int j = 0; j < 4; ++j)
            s_h[(tw * 4 + j) * 264 + ch] = h16(lrelu(vv[j]));
    }
    __syncthreads();
    u32* gh = (u32*)g_xh;
    const u32* sh = (const u32*)s_h;
    for (int i = tid; i < 32 * 128; i += 256) {
        int t = i >> 7, j = i & 127;
        gh[((size_t)(b * TL + t0 + t)) * 128 + j] = sh[t * 132 + j];
    }
}

// ---------------- chunk producers (512 threads) ----------------
__device__ __forceinline__ void issueA(u32 sbase, const u16* wh, const u16* wl,
                                       int kc, int mt, int tid) {
#pragma unroll
    for (int i = 0; i < 4; ++i) {
        int id = tid + i * NTHR;               // 0..2047
        int plane = id >> 10, idx = id & 1023, r = idx >> 3, u = idx & 7;
        const u16* src = (plane ? wl : wh) + (size_t)(mt * 128 + r) * KTOT + kc * KC + u * 8;
        u32 dst = sbase + plane * 16384 + r * 128 + ((u ^ (r & 7)) << 4);
        cpa16(dst, src, 16);
    }
}
__device__ __forceinline__ void issueB(u32 sbase, const u16* xh, int mode, int kc,
                                       int b, int t0, const int* s_ip, const int* s_if, int tid) {
    int sec = kc >> 2, ch0 = (kc & 3) << 6;
#pragma unroll
    for (int i = 0; i < 2; ++i) {
        int id = tid + i * NTHR;               // 0..1023
        int r = id >> 3, u = id & 7;
        int st; u32 sz = 16;
        if (mode == 0) {       // k1: xt / xP / xF
            st = (sec == 0) ? (t0 + r) : ((sec == 1) ? s_ip[r] : s_if[r]);
            if (st < 0) { st = 0; sz = 0; }
        } else {               // k2: conv3 taps
            st = t0 + r - 1 + sec;
            if (st < 0 || st >= TL) { st = 0; sz = 0; }
        }
        const u16* src = xh + ((size_t)(b * TL + st)) * CC + ch0 + u * 8;
        u32 dst = sbase + BH_OFF + r * 128 + ((u ^ (r & 7)) << 4);
        cpa16(dst, src, sz);
    }
}

// ---------------- MMA core: warp tile 32x32, 16 warps, 2 passes ----------------
__device__ __forceinline__ void compute_chunk(u32 base, const int* aoff, const int* asw,
                                              const int* boff, const int* bsw,
                                              int lsel, int ubsel, float acc[2][4][4]) {
#pragma unroll
    for (int s = 0; s < 4; ++s) {
        u32 ah[2][4], al[2][4], bh[2][4];
#pragma unroll
        for (int mf = 0; mf < 2; ++mf) {
            u32 ua = (u32)(((2 * s + lsel) ^ asw[mf]) << 4);
            ldm4(base + AH_OFF + aoff[mf] + ua, ah[mf]);
            ldm4(base + AL_OFF + aoff[mf] + ua, al[mf]);
        }
#pragma unroll
        for (int nf = 0; nf < 2; ++nf) {
            u32 ub = (u32)(((2 * s + ubsel) ^ bsw[nf]) << 4);
            ldm4(base + BH_OFF + boff[nf] + ub, bh[nf]);
        }
#pragma unroll
        for (int mf = 0; mf < 2; ++mf)
#pragma unroll
            for (int nb = 0; nb < 4; ++nb) {
                const u32* bhf = &bh[nb >> 1][(nb & 1) * 2];
                mma16816(acc[mf][nb], ah[mf], bhf);
                mma16816(acc[mf][nb], al[mf], bhf);
            }
    }
}

__device__ __forceinline__ void frag_setup(int wm, int wn, int lid,
                                           int* aoff, int* asw, int* boff, int* bsw) {
#pragma unroll
    for (int mf = 0; mf < 2; ++mf) {
        int r = wm * 32 + mf * 16 + (lid & 15);
        aoff[mf] = r * 128; asw[mf] = r & 7;
    }
#pragma unroll
    for (int nf = 0; nf < 2; ++nf) {
        int r = wn * 32 + nf * 16 + (lid & 7) + 8 * (lid >> 4);
        boff[nf] = r * 128; bsw[nf] = r & 7;
    }
}

// main loop shared by k1/k2 (mode selects B addressing)
#define GEMM_LOOP(WH, WL, XSRC, MODE)                                              \
    issueA(sb, WH, WL, 0, mt, tid);                                                \
    issueB(sb, XSRC, MODE, 0, b, t0, s_ip, s_if, tid);                             \
    cpa_commit();                                                                  \
    issueA(sb + BUFSZ, WH, WL, 1, mt, tid);                                        \
    issueB(sb + BUFSZ, XSRC, MODE, 1, b, t0, s_ip, s_if, tid);                     \
    cpa_commit();                                                                  \
    for (int kc = 0; kc < NCHK; ++kc) {                                            \
        if (kc == NCHK - 1) cpa_wait0(); else cpa_wait1();                         \
        __syncthreads();                                                           \
        if (kc + 2 < NCHK) {                                                       \
            u32 nb_ = sb + ((kc + 2) % 3) * BUFSZ;                                 \
            issueA(nb_, WH, WL, kc + 2, mt, tid);                                  \
            issueB(nb_, XSRC, MODE, kc + 2, b, t0, s_ip, s_if, tid);               \
            cpa_commit();                                                          \
        }                                                                          \
        compute_chunk(sb + (kc % 3) * BUFSZ, aoff, asw, boff, bsw, lsel, ubsel, acc); \
    }

// ---------------- stage 1 GEMM kernel ----------------
__global__ __launch_bounds__(NTHR, 1)
void k1(const float* __restrict__ dfac, const float* __restrict__ bC,
        const float* __restrict__ bP, const float* __restrict__ bF,
        int iter, float dilation) {
    extern __shared__ __align__(1024) unsigned char dynsm[];
    __shared__ int s_ip[128], s_if[128];

    const int tid = threadIdx.x, wid = tid >> 5, lid = tid & 31;
    const int wm = wid & 3, wn = wid >> 2;
    const int b = blockIdx.z, mt = blockIdx.y, t0 = blockIdx.x * 128;
    const u32 sb = sm2u(dynsm);

    if (tid < 128) {
        int t = t0 + tid;
        float dil = dfac[b * TL + t] * dilation;
        int ip = __float2int_rn((float)t - dil);
        int iF = __float2int_rn((float)t + dil);
        s_ip[tid] = (ip >= 0) ? ip : -1;
        s_if[tid] = (iF < TL) ? iF : -1;
    }
    __syncthreads();

    const u16* wh = g_w1h + (size_t)iter * CC * KTOT;
    const u16* wl = g_w1l + (size_t)iter * CC * KTOT;

    int aoff[2], asw[2], boff[2], bsw[2];
    int lsel = lid >> 4, ubsel = (lid >> 3) & 1;
    frag_setup(wm, wn, lid, aoff, asw, boff, bsw);

    float acc[2][4][4];
#pragma unroll
    for (int a = 0; a < 2; ++a)
#pragma unroll
        for (int c = 0; c < 4; ++c)
#pragma unroll
            for (int d = 0; d < 4; ++d) acc[a][c][d] = 0.f;

    GEMM_LOOP(wh, wl, g_xh, 0)

    // epilogue: bias + lrelu + fp16, transpose via smem, store [t][ch] plane
    __syncthreads();
    u16* ep = (u16*)dynsm;   // [128 cols(t)][132 rows(oc)] u16
    int gq = lid >> 2, cq = 2 * (lid & 3);
#pragma unroll
    for (int mf = 0; mf < 2; ++mf) {
        int r0 = wm * 32 + mf * 16 + gq, r1 = r0 + 8;
        int g0 = mt * 128 + r0, g1 = mt * 128 + r1;
        float bs0 = bC[g0] + bP[g0] + bF[g0];
        float bs1 = bC[g1] + bP[g1] + bF[g1];
#pragma unroll
        for (int nb = 0; nb < 4; ++nb) {
            int c = wn * 32 + nb * 8 + cq;
            const float* a = acc[mf][nb];
            ep[c * 132 + r0]       = h16(lrelu(a[0] + bs0));
            ep[(c + 1) * 132 + r0] = h16(lrelu(a[1] + bs0));
            ep[c * 132 + r1]       = h16(lrelu(a[2] + bs1));
            ep[(c + 1) * 132 + r1] = h16(lrelu(a[3] + bs1));
        }
    }
    __syncthreads();
    u32* yh = (u32*)g_yh;
    const u32* epu = (const u32*)dynsm;
    for (int i = tid; i < 128 * 64; i += NTHR) {
        int t = i >> 6, j = i & 63;
        yh[((size_t)(b * TL + t0 + t)) * 128 + mt * 64 + j] = epu[t * 66 + j];
    }
}

// ---------------- stage 2 GEMM kernel (conv3 + residual + write next-iter xh) ----------------
__global__ __launch_bounds__(NTHR, 1)
void k2(float* __restrict__ xo, const float* __restrict__ bA, int iter) {
    extern __shared__ __align__(1024) unsigned char dynsm[];

    const int tid = threadIdx.x, wid = tid >> 5, lid = tid & 31;
    const int wm = wid & 3, wn = wid >> 2;
    const int b = blockIdx.z, mt = blockIdx.y, t0 = blockIdx.x * 128;
    const u32 sb = sm2u(dynsm);
    const int* s_ip = 0; const int* s_if = 0;   // unused in mode 1

    const u16* wh = g_w2h + (size_t)iter * CC * KTOT;
    const u16* wl = g_w2l + (size_t)iter * CC * KTOT;

    int aoff[2], asw[2], boff[2], bsw[2];
    int lsel = lid >> 4, ubsel = (lid >> 3) & 1;
    frag_setup(wm, wn, lid, aoff, asw, boff, bsw);

    float acc[2][4][4];
#pragma unroll
    for (int a = 0; a < 2; ++a)
#pragma unroll
        for (int c = 0; c < 4; ++c)
#pragma unroll
            for (int d = 0; d < 4; ++d) acc[a][c][d] = 0.f;

    GEMM_LOOP(wh, wl, g_yh, 1)

    // epilogue: bias + residual -> xo; also lrelu+fp16 transpose -> g_xh (next iter)
    __syncthreads();
    u16* ep = (u16*)dynsm;
    int gq = lid >> 2, cq = 2 * (lid & 3);
#pragma unroll
    for (int mf = 0; mf < 2; ++mf) {
        int r0 = wm * 32 + mf * 16 + gq, r1 = r0 + 8;
        int g0 = mt * 128 + r0, g1 = mt * 128 + r1;
        float bs0 = bA[g0], bs1 = bA[g1];
        float* p0b = xo + ((size_t)(b * CC + g0)) * TL + t0;
        float* p1b = xo + ((size_t)(b * CC + g1)) * TL + t0;
#pragma unroll
        for (int nb = 0; nb < 4; ++nb) {
            int c = wn * 32 + nb * 8 + cq;
            const float* a = acc[mf][nb];
            float2* q0 = (float2*)(p0b + c);
            float2 v0 = *q0;
            v0.x += a[0] + bs0; v0.y += a[1] + bs0;
            *q0 = v0;
            float2* q1 = (float2*)(p1b + c);
            float2 v1 = *q1;
            v1.x += a[2] + bs1; v1.y += a[3] + bs1;
            *q1 = v1;
            ep[c * 132 + r0]       = h16(lrelu(v0.x));
            ep[(c + 1) * 132 + r0] = h16(lrelu(v0.y));
            ep[c * 132 + r1]       = h16(lrelu(v1.x));
            ep[(c + 1) * 132 + r1] = h16(lrelu(v1.y));
        }
    }
    __syncthreads();
    u32* xh = (u32*)g_xh;
    const u32* epu = (const u32*)dynsm;
    for (int i = tid; i < 128 * 64; i += NTHR) {
        int t = i >> 6, j = i & 63;
        xh[((size_t)(b * TL + t0 + t)) * 128 + mt * 64 + j] = epu[t * 66 + j];
    }
}

// ---------------- launch ----------------
extern "C" void kernel_launch(void* const* d_in, const int* in_sizes, int n_in,
                              void* d_out, int out_size) {
    const float* x  = (const float*)d_in[0];
    const float* d  = (const float*)d_in[1];
    const float* WC = (const float*)d_in[2];
    const float* bC = (const float*)d_in[3];
    const float* WP = (const float*)d_in[4];
    const float* bP = (const float*)d_in[5];
    const float* WF = (const float*)d_in[6];
    const float* bF = (const float*)d_in[7];
    const float* WA = (const float*)d_in[8];
    const float* bA = (const float*)d_in[9];
    float* xo = (float*)d_out;

    cudaMemcpyAsync(xo, x, (size_t)BB * CC * TL * sizeof(float),
                    cudaMemcpyDeviceToDevice);

    prep_w<<<(2 * 3 * CC * KTOT + 255) / 256, 256>>>(WC, WP, WF, WA);

    const int DSMEM = 3 * BUFSZ;   // 144 KB
    cudaFuncSetAttribute((const void*)k1, cudaFuncAttributeMaxDynamicSharedMemorySize, DSMEM);
    cudaFuncSetAttribute((const void*)k2, cudaFuncAttributeMaxDynamicSharedMemorySize, DSMEM);

    dim3 gprex(TL / 32, BB);
    dim3 grid(TL / 128, 2, BB);
    const float dils[3] = {1.0f, 2.0f, 4.0f};
    prex<<<gprex, 256>>>(xo);
    for (int i = 0; i < 3; ++i) {
        k1<<<grid, NTHR, DSMEM>>>(d, bC + i * 256, bP + i * 256, bF + i * 256, i, dils[i]);
        k2<<<grid, NTHR, DSMEM>>>(xo, bA + i * 256, i);
    }
}

// round 6
// speedup vs baseline: 4.8304x; 1.1570x over previous
#include <cuda_runtime.h>
#include <cuda_fp16.h>

#define TL   8192
#define CC   256
#define BB   8
#define KTOT 768
#define KC   64
#define NCHK 12
#define NTHR 256

typedef unsigned u32;
typedef unsigned short u16;

// ---------------- device scratch (fp16 planes) ----------------
__device__ u16 g_w1h[3*CC*KTOT], g_w1l[3*CC*KTOT];   // stage1 W split [iter][oc][K]
__device__ u16 g_w2h[3*CC*KTOT], g_w2l[3*CC*KTOT];   // stage2 W split
__device__ u16 g_xh[BB*TL*CC];                        // fp16(lrelu(x)), [b][t][ch]
__device__ u16 g_yh[BB*TL*CC];                        // fp16(lrelu(stage1 out))

// ---------------- helpers ----------------
__device__ __forceinline__ u32 sm2u(const void* p) {
    u32 a;
    asm("{ .reg .u64 t; cvta.to.shared.u64 t, %1; cvt.u32.u64 %0, t; }" : "=r"(a) : "l"(p));
    return a;
}
__device__ __forceinline__ void cpa16(u32 s, const void* g, u32 sz) {
    asm volatile("cp.async.cg.shared.global [%0], [%1], 16, %2;" :: "r"(s), "l"(g), "r"(sz));
}
__device__ __forceinline__ void cpa_commit() { asm volatile("cp.async.commit_group;"); }
__device__ __forceinline__ void cpa_wait0()  { asm volatile("cp.async.wait_group 0;"); }

__device__ __forceinline__ void ldm4(u32 addr, u32* r) {
    asm volatile("ldmatrix.sync.aligned.m8n8.x4.shared.b16 {%0,%1,%2,%3}, [%4];"
                 : "=r"(r[0]), "=r"(r[1]), "=r"(r[2]), "=r"(r[3]) : "r"(addr));
}
__device__ __forceinline__ void mma16816(float* d, const u32* a, const u32* b) {
    asm volatile("mma.sync.aligned.m16n8k16.row.col.f32.f16.f16.f32 "
                 "{%0,%1,%2,%3}, {%4,%5,%6,%7}, {%8,%9}, {%0,%1,%2,%3};"
                 : "+f"(d[0]), "+f"(d[1]), "+f"(d[2]), "+f"(d[3])
                 : "r"(a[0]), "r"(a[1]), "r"(a[2]), "r"(a[3]), "r"(b[0]), "r"(b[1]));
}
__device__ __forceinline__ void split2h(float v, u16& h, u16& l) {
    __half hb = __float2half_rn(v);
    float r = v - __half2float(hb);
    h = __half_as_ushort(hb);
    l = __half_as_ushort(__float2half_rn(r));
}
__device__ __forceinline__ u16 h16(float v) { return __half_as_ushort(__float2half_rn(v)); }
__device__ __forceinline__ float lrelu(float v) { return fmaxf(v, 0.1f * v); }

// smem tile layout: [128 rows][8 x 16B units], unit swizzle u ^= (row & 7)
#define AH_OFF 0
#define AL_OFF 16384
#define BH_OFF 32768
#define BUFSZ  49152    // Ah 16K + Al 16K + Bh 16K

// ---------------- prep: split all weights into fp16 h/l ----------------
__global__ void prep_w(const float* __restrict__ WC, const float* __restrict__ WP,
                       const float* __restrict__ WF, const float* __restrict__ WA) {
    int id = blockIdx.x * 256 + threadIdx.x;
    if (id >= 2 * 3 * CC * KTOT) return;
    int K = id % KTOT;
    int rest = id / KTOT;
    int oc = rest & 255;
    rest >>= 8;
    int i = rest % 3, stage = rest / 3;
    int sec = K >> 8, ch = K & 255;
    float w;
    if (stage == 0) {
        const float* W = (sec == 0) ? WC : (sec == 1) ? WP : WF;
        w = W[i * 65536 + oc * 256 + ch];
    } else {
        w = WA[(i * 65536 + oc * 256 + ch) * 3 + sec];
    }
    u16 h, l; split2h(w, h, l);
    int dst = (i * CC + oc) * KTOT + K;
    if (stage == 0) { g_w1h[dst] = h; g_w1l[dst] = l; }
    else            { g_w2h[dst] = h; g_w2l[dst] = l; }
}

// ---------------- prex: lrelu + fp16 + transpose x -> g_xh [b][t][ch] (once) ----------------
__global__ __launch_bounds__(256) void prex(const float* __restrict__ xo) {
    __shared__ u16 s_h[32 * 264];
    int b = blockIdx.y, t0 = blockIdx.x * 32;
    int tid = threadIdx.x;
    int chl = tid >> 3, tw = tid & 7;
    for (int cp = 0; cp < 8; ++cp) {
        int ch = cp * 32 + chl;
        const float4 v = *(const float4*)(xo + ((size_t)(b * 256 + ch)) * TL + t0 + tw * 4);
        float vv[4] = {v.x, v.y, v.z, v.w};
#pragma unroll
        for (int j = 0; j < 4; ++j)
            s_h[(tw * 4 + j) * 264 + ch] = h16(lrelu(vv[j]));
    }
    __syncthreads();
    u32* gh = (u32*)g_xh;
    const u32* sh = (const u32*)s_h;
    for (int i = tid; i < 32 * 128; i += 256) {
        int t = i >> 7, j = i & 127;
        gh[((size_t)(b * TL + t0 + t)) * 128 + j] = sh[t * 132 + j];
    }
}

// ---------------- chunk producers (256 threads) ----------------
__device__ __forceinline__ void issueA(u32 sbase, const u16* wh, const u16* wl,
                                       int kc, int mt, int tid) {
#pragma unroll
    for (int i = 0; i < 8; ++i) {
        int id = tid + i * NTHR;               // 0..2047
        int plane = id >> 10, idx = id & 1023, r = idx >> 3, u = idx & 7;
        const u16* src = (plane ? wl : wh) + (size_t)(mt * 128 + r) * KTOT + kc * KC + u * 8;
        u32 dst = sbase + plane * 16384 + r * 128 + ((u ^ (r & 7)) << 4);
        cpa16(dst, src, 16);
    }
}
__device__ __forceinline__ void issueB(u32 sbase, const u16* xh, int mode, int kc,
                                       int b, int t0, const int* s_ip, const int* s_if, int tid) {
    int sec = kc >> 2, ch0 = (kc & 3) << 6;
#pragma unroll
    for (int i = 0; i < 4; ++i) {
        int id = tid + i * NTHR;               // 0..1023
        int r = id >> 3, u = id & 7;
        int st; u32 sz = 16;
        if (mode == 0) {       // k1: xt / xP / xF
            st = (sec == 0) ? (t0 + r) : ((sec == 1) ? s_ip[r] : s_if[r]);
            if (st < 0) { st = 0; sz = 0; }
        } else {               // k2: conv3 taps
            st = t0 + r - 1 + sec;
            if (st < 0 || st >= TL) { st = 0; sz = 0; }
        }
        const u16* src = xh + ((size_t)(b * TL + st)) * CC + ch0 + u * 8;
        u32 dst = sbase + BH_OFF + r * 128 + ((u ^ (r & 7)) << 4);
        cpa16(dst, src, sz);
    }
}

// ---------------- MMA core: warp tile 32x64, 8 warps (4x2), 2 passes ----------------
__device__ __forceinline__ void compute_chunk(u32 base, const int* aoff, const int* asw,
                                              const int* boff, const int* bsw,
                                              int lsel, int ubsel, float acc[2][8][4]) {
#pragma unroll
    for (int s = 0; s < 4; ++s) {
        u32 ah[2][4], al[2][4], bh[4][4];
#pragma unroll
        for (int mf = 0; mf < 2; ++mf) {
            u32 ua = (u32)(((2 * s + lsel) ^ asw[mf]) << 4);
            ldm4(base + AH_OFF + aoff[mf] + ua, ah[mf]);
            ldm4(base + AL_OFF + aoff[mf] + ua, al[mf]);
        }
#pragma unroll
        for (int nf = 0; nf < 4; ++nf) {
            u32 ub = (u32)(((2 * s + ubsel) ^ bsw[nf]) << 4);
            ldm4(base + BH_OFF + boff[nf] + ub, bh[nf]);
        }
#pragma unroll
        for (int mf = 0; mf < 2; ++mf)
#pragma unroll
            for (int nb = 0; nb < 8; ++nb) {
                const u32* bhf = &bh[nb >> 1][(nb & 1) * 2];
                mma16816(acc[mf][nb], ah[mf], bhf);
                mma16816(acc[mf][nb], al[mf], bhf);
            }
    }
}

__device__ __forceinline__ void frag_setup(int wm, int wn, int lid,
                                           int* aoff, int* asw, int* boff, int* bsw) {
#pragma unroll
    for (int mf = 0; mf < 2; ++mf) {
        int r = wm * 32 + mf * 16 + (lid & 15);
        aoff[mf] = r * 128; asw[mf] = r & 7;
    }
#pragma unroll
    for (int nf = 0; nf < 4; ++nf) {
        int r = wn * 64 + nf * 16 + (lid & 7) + 8 * (lid >> 4);
        boff[nf] = r * 128; bsw[nf] = r & 7;
    }
}

// main loop shared by k1/k2 (mode selects B addressing); 2-stage pipeline
#define GEMM_LOOP(WH, WL, XSRC, MODE)                                              \
    issueA(sb, WH, WL, 0, mt, tid);                                                \
    issueB(sb, XSRC, MODE, 0, b, t0, s_ip, s_if, tid);                             \
    cpa_commit();                                                                  \
    for (int kc = 0; kc < NCHK; ++kc) {                                            \
        cpa_wait0();                                                               \
        __syncthreads();                                                           \
        if (kc + 1 < NCHK) {                                                       \
            u32 nb_ = sb + ((kc + 1) & 1) * BUFSZ;                                 \
            issueA(nb_, WH, WL, kc + 1, mt, tid);                                  \
            issueB(nb_, XSRC, MODE, kc + 1, b, t0, s_ip, s_if, tid);               \
            cpa_commit();                                                          \
        }                                                                          \
        compute_chunk(sb + (kc & 1) * BUFSZ, aoff, asw, boff, bsw, lsel, ubsel, acc); \
    }

// ---------------- stage 1 GEMM kernel ----------------
__global__ __launch_bounds__(NTHR, 2)
void k1(const float* __restrict__ dfac, const float* __restrict__ bC,
        const float* __restrict__ bP, const float* __restrict__ bF,
        int iter, float dilation) {
    extern __shared__ __align__(1024) unsigned char dynsm[];
    __shared__ int s_ip[128], s_if[128];

    const int tid = threadIdx.x, wid = tid >> 5, lid = tid & 31;
    const int wm = wid & 3, wn = wid >> 2;
    const int b = blockIdx.z, mt = blockIdx.y, t0 = blockIdx.x * 128;
    const u32 sb = sm2u(dynsm);

    if (tid < 128) {
        int t = t0 + tid;
        float dil = dfac[b * TL + t] * dilation;
        int ip = __float2int_rn((float)t - dil);
        int iF = __float2int_rn((float)t + dil);
        s_ip[tid] = (ip >= 0) ? ip : -1;
        s_if[tid] = (iF < TL) ? iF : -1;
    }
    __syncthreads();

    const u16* wh = g_w1h + (size_t)iter * CC * KTOT;
    const u16* wl = g_w1l + (size_t)iter * CC * KTOT;

    int aoff[2], asw[2], boff[4], bsw[4];
    int lsel = lid >> 4, ubsel = (lid >> 3) & 1;
    frag_setup(wm, wn, lid, aoff, asw, boff, bsw);

    float acc[2][8][4];
#pragma unroll
    for (int a = 0; a < 2; ++a)
#pragma unroll
        for (int c = 0; c < 8; ++c)
#pragma unroll
            for (int d = 0; d < 4; ++d) acc[a][c][d] = 0.f;

    GEMM_LOOP(wh, wl, g_xh, 0)

    // epilogue: bias + lrelu + fp16, transpose via smem, store [t][ch] plane
    __syncthreads();
    u16* ep = (u16*)dynsm;   // [128 cols(t)][132 rows(oc)] u16
    int gq = lid >> 2, cq = 2 * (lid & 3);
#pragma unroll
    for (int mf = 0; mf < 2; ++mf) {
        int r0 = wm * 32 + mf * 16 + gq, r1 = r0 + 8;
        int g0 = mt * 128 + r0, g1 = mt * 128 + r1;
        float bs0 = bC[g0] + bP[g0] + bF[g0];
        float bs1 = bC[g1] + bP[g1] + bF[g1];
#pragma unroll
        for (int nb = 0; nb < 8; ++nb) {
            int c = wn * 64 + nb * 8 + cq;
            const float* a = acc[mf][nb];
            ep[c * 132 + r0]       = h16(lrelu(a[0] + bs0));
            ep[(c + 1) * 132 + r0] = h16(lrelu(a[1] + bs0));
            ep[c * 132 + r1]       = h16(lrelu(a[2] + bs1));
            ep[(c + 1) * 132 + r1] = h16(lrelu(a[3] + bs1));
        }
    }
    __syncthreads();
    u32* yh = (u32*)g_yh;
    const u32* epu = (const u32*)dynsm;
    for (int i = tid; i < 128 * 64; i += NTHR) {
        int t = i >> 6, j = i & 63;
        yh[((size_t)(b * TL + t0 + t)) * 128 + mt * 64 + j] = epu[t * 66 + j];
    }
}

// ---------------- stage 2 GEMM kernel (conv3 + residual + write next-iter xh) ----------------
__global__ __launch_bounds__(NTHR, 2)
void k2(float* __restrict__ xo, const float* __restrict__ bA, int iter) {
    extern __shared__ __align__(1024) unsigned char dynsm[];

    const int tid = threadIdx.x, wid = tid >> 5, lid = tid & 31;
    const int wm = wid & 3, wn = wid >> 2;
    const int b = blockIdx.z, mt = blockIdx.y, t0 = blockIdx.x * 128;
    const u32 sb = sm2u(dynsm);
    const int* s_ip = 0; const int* s_if = 0;   // unused in mode 1

    const u16* wh = g_w2h + (size_t)iter * CC * KTOT;
    const u16* wl = g_w2l + (size_t)iter * CC * KTOT;

    int aoff[2], asw[2], boff[4], bsw[4];
    int lsel = lid >> 4, ubsel = (lid >> 3) & 1;
    frag_setup(wm, wn, lid, aoff, asw, boff, bsw);

    float acc[2][8][4];
#pragma unroll
    for (int a = 0; a < 2; ++a)
#pragma unroll
        for (int c = 0; c < 8; ++c)
#pragma unroll
            for (int d = 0; d < 4; ++d) acc[a][c][d] = 0.f;

    GEMM_LOOP(wh, wl, g_yh, 1)

    // epilogue: bias + residual -> xo; also lrelu+fp16 transpose -> g_xh (next iter)
    __syncthreads();
    u16* ep = (u16*)dynsm;
    int gq = lid >> 2, cq = 2 * (lid & 3);
#pragma unroll
    for (int mf = 0; mf < 2; ++mf) {
        int r0 = wm * 32 + mf * 16 + gq, r1 = r0 + 8;
        int g0 = mt * 128 + r0, g1 = mt * 128 + r1;
        float bs0 = bA[g0], bs1 = bA[g1];
        float* p0b = xo + ((size_t)(b * CC + g0)) * TL + t0;
        float* p1b = xo + ((size_t)(b * CC + g1)) * TL + t0;
#pragma unroll
        for (int nb = 0; nb < 8; ++nb) {
            int c = wn * 64 + nb * 8 + cq;
            const float* a = acc[mf][nb];
            float2* q0 = (float2*)(p0b + c);
            float2 v0 = *q0;
            v0.x += a[0] + bs0; v0.y += a[1] + bs0;
            *q0 = v0;
            float2* q1 = (float2*)(p1b + c);
            float2 v1 = *q1;
            v1.x += a[2] + bs1; v1.y += a[3] + bs1;
            *q1 = v1;
            ep[c * 132 + r0]       = h16(lrelu(v0.x));
            ep[(c + 1) * 132 + r0] = h16(lrelu(v0.y));
            ep[c * 132 + r1]       = h16(lrelu(v1.x));
            ep[(c + 1) * 132 + r1] = h16(lrelu(v1.y));
        }
    }
    __syncthreads();
    u32* xh = (u32*)g_xh;
    const u32* epu = (const u32*)dynsm;
    for (int i = tid; i < 128 * 64; i += NTHR) {
        int t = i >> 6, j = i & 63;
        xh[((size_t)(b * TL + t0 + t)) * 128 + mt * 64 + j] = epu[t * 66 + j];
    }
}

// ---------------- launch ----------------
extern "C" void kernel_launch(void* const* d_in, const int* in_sizes, int n_in,
                              void* d_out, int out_size) {
    const float* x  = (const float*)d_in[0];
    const float* d  = (const float*)d_in[1];
    const float* WC = (const float*)d_in[2];
    const float* bC = (const float*)d_in[3];
    const float* WP = (const float*)d_in[4];
    const float* bP = (const float*)d_in[5];
    const float* WF = (const float*)d_in[6];
    const float* bF = (const float*)d_in[7];
    const float* WA = (const float*)d_in[8];
    const float* bA = (const float*)d_in[9];
    float* xo = (float*)d_out;

    cudaMemcpyAsync(xo, x, (size_t)BB * CC * TL * sizeof(float),
                    cudaMemcpyDeviceToDevice);

    prep_w<<<(2 * 3 * CC * KTOT + 255) / 256, 256>>>(WC, WP, WF, WA);

    const int DSMEM = 2 * BUFSZ;   // 96 KB
    cudaFuncSetAttribute((const void*)k1, cudaFuncAttributeMaxDynamicSharedMemorySize, DSMEM);
    cudaFuncSetAttribute((const void*)k2, cudaFuncAttributeMaxDynamicSharedMemorySize, DSMEM);

    dim3 gprex(TL / 32, BB);
    dim3 grid(TL / 128, 2, BB);
    const float dils[3] = {1.0f, 2.0f, 4.0f};
    prex<<<gprex, 256>>>(xo);
    for (int i = 0; i < 3; ++i) {
        k1<<<grid, NTHR, DSMEM>>>(d, bC + i * 256, bP + i * 256, bF + i * 256, i, dils[i]);
        k2<<<grid, NTHR, DSMEM>>>(xo, bA + i * 256, i);
    }
}

// round 7
// speedup vs baseline: 7.4490x; 1.5421x over previous
#include <cuda_runtime.h>
#include <cuda_fp16.h>

#define TL   8192
#define CC   256
#define BB   8
#define KTOT 768
#define KC   64
#define NCHK 12
#define NTHR 256
#define NSTG 4

typedef unsigned u32;
typedef unsigned short u16;

// ---------------- device scratch ----------------
// weights pre-packed in mma A-fragment order:
// [iter][mt][wm][mf][kc][s][lane] -> uint4 (8 fp16 = one m16k16 A fragment per lane)
__device__ uint4 g_w1f[3*2*4*2*12*4*32];
__device__ uint4 g_w2f[3*2*4*2*12*4*32];
__device__ u16 g_xh[BB*TL*CC];   // fp16(lrelu(x)), [b][t][ch]
__device__ u16 g_yh[BB*TL*CC];   // fp16(lrelu(stage1 out))

// ---------------- helpers ----------------
__device__ __forceinline__ u32 sm2u(const void* p) {
    u32 a;
    asm("{ .reg .u64 t; cvta.to.shared.u64 t, %1; cvt.u32.u64 %0, t; }" : "=r"(a) : "l"(p));
    return a;
}
__device__ __forceinline__ void cpa16(u32 s, const void* g, u32 sz) {
    asm volatile("cp.async.cg.shared.global [%0], [%1], 16, %2;" :: "r"(s), "l"(g), "r"(sz));
}
__device__ __forceinline__ void cpa_commit() { asm volatile("cp.async.commit_group;"); }
__device__ __forceinline__ void cpa_wait0()  { asm volatile("cp.async.wait_group 0;"); }
__device__ __forceinline__ void cpa_wait1()  { asm volatile("cp.async.wait_group 1;"); }
__device__ __forceinline__ void cpa_wait2()  { asm volatile("cp.async.wait_group 2;"); }

__device__ __forceinline__ void ldm4(u32 addr, u32* r) {
    asm volatile("ldmatrix.sync.aligned.m8n8.x4.shared.b16 {%0,%1,%2,%3}, [%4];"
                 : "=r"(r[0]), "=r"(r[1]), "=r"(r[2]), "=r"(r[3]) : "r"(addr));
}
__device__ __forceinline__ void mma16816(float* d, const u32* a, const u32* b) {
    asm volatile("mma.sync.aligned.m16n8k16.row.col.f32.f16.f16.f32 "
                 "{%0,%1,%2,%3}, {%4,%5,%6,%7}, {%8,%9}, {%0,%1,%2,%3};"
                 : "+f"(d[0]), "+f"(d[1]), "+f"(d[2]), "+f"(d[3])
                 : "r"(a[0]), "r"(a[1]), "r"(a[2]), "r"(a[3]), "r"(b[0]), "r"(b[1]));
}
__device__ __forceinline__ u16 h16(float v) { return __half_as_ushort(__float2half_rn(v)); }
__device__ __forceinline__ float lrelu(float v) { return fmaxf(v, 0.1f * v); }

#define BUFSZ 16384   // one B tile: 128 t-rows x 64 ch fp16

// ---------------- prep: pack weights into A-fragment order ----------------
__global__ void prep_w(const float* __restrict__ WC, const float* __restrict__ WP,
                       const float* __restrict__ WF, const float* __restrict__ WA) {
    int id = blockIdx.x * 256 + threadIdx.x;
    if (id >= 2 * 3 * 2 * 4 * 2 * 12 * 4 * 32) return;   // 147456
    int lane = id & 31; int rest = id >> 5;
    int s  = rest & 3;  rest >>= 2;
    int kc = rest % 12; rest /= 12;
    int mf = rest & 1;  rest >>= 1;
    int wm = rest & 3;  rest >>= 2;
    int mt = rest & 1;  rest >>= 1;
    int i = rest % 3, stage = rest / 3;

    int oc0 = mt * 128 + wm * 32 + mf * 16 + (lane >> 2);
    int k0  = kc * 64 + s * 16 + (lane & 3) * 2;

    float w[2][2][2];   // [oc +0/+8][k +0/+8][k +0/+1]
#pragma unroll
    for (int ro = 0; ro < 2; ++ro)
#pragma unroll
        for (int ko = 0; ko < 2; ++ko)
#pragma unroll
            for (int kk = 0; kk < 2; ++kk) {
                int oc = oc0 + ro * 8;
                int k  = k0 + ko * 8 + kk;
                int sec = k >> 8, ch = k & 255;
                float v;
                if (stage == 0) {
                    const float* W = (sec == 0) ? WC : (sec == 1) ? WP : WF;
                    v = W[i * 65536 + oc * 256 + ch];
                } else {
                    v = WA[(i * 65536 + oc * 256 + ch) * 3 + sec];
                }
                w[ro][ko][kk] = v;
            }
    uint4 out;
    out.x = (u32)h16(w[0][0][0]) | ((u32)h16(w[0][0][1]) << 16);
    out.y = (u32)h16(w[1][0][0]) | ((u32)h16(w[1][0][1]) << 16);
    out.z = (u32)h16(w[0][1][0]) | ((u32)h16(w[0][1][1]) << 16);
    out.w = (u32)h16(w[1][1][0]) | ((u32)h16(w[1][1][1]) << 16);
    int dst = (((((i * 2 + mt) * 4 + wm) * 2 + mf) * 12 + kc) * 4 + s) * 32 + lane;
    if (stage == 0) g_w1f[dst] = out; else g_w2f[dst] = out;
}

// ---------------- prex: lrelu + fp16 + transpose x -> g_xh [b][t][ch] (once) ----------------
__global__ __launch_bounds__(256) void prex(const float* __restrict__ xo) {
    __shared__ u16 s_h[32 * 264];
    int b = blockIdx.y, t0 = blockIdx.x * 32;
    int tid = threadIdx.x;
    int chl = tid >> 3, tw = tid & 7;
    for (int cp = 0; cp < 8; ++cp) {
        int ch = cp * 32 + chl;
        const float4 v = *(const float4*)(xo + ((size_t)(b * 256 + ch)) * TL + t0 + tw * 4);
        float vv[4] = {v.x, v.y, v.z, v.w};
#pragma unroll
        for (int j = 0; j < 4; ++j)
            s_h[(tw * 4 + j) * 264 + ch] = h16(lrelu(vv[j]));
    }
    __syncthreads();
    u32* gh = (u32*)g_xh;
    const u32* sh = (const u32*)s_h;
    for (int i = tid; i < 32 * 128; i += 256) {
        int t = i >> 7, j = i & 127;
        gh[((size_t)(b * TL + t0 + t)) * 128 + j] = sh[t * 132 + j];
    }
}

// ---------------- B producer: one 128x64ch fp16 tile via cp.async ----------------
__device__ __forceinline__ void issueB(u32 sbase, const u16* xh, int mode, int kc,
                                       int b, int t0, const int* s_ip, const int* s_if, int tid) {
    int sec = kc >> 2, ch0 = (kc & 3) << 6;
#pragma unroll
    for (int i = 0; i < 4; ++i) {
        int id = tid + i * NTHR;               // 0..1023
        int r = id >> 3, u = id & 7;
        int st; u32 sz = 16;
        if (mode == 0) {       // k1: xt / xP / xF
            st = (sec == 0) ? (t0 + r) : ((sec == 1) ? s_ip[r] : s_if[r]);
            if (st < 0) { st = 0; sz = 0; }
        } else {               // k2: conv3 taps
            st = t0 + r - 1 + sec;
            if (st < 0 || st >= TL) { st = 0; sz = 0; }
        }
        const u16* src = xh + ((size_t)(b * TL + st)) * CC + ch0 + u * 8;
        u32 dst = sbase + r * 128 + ((u ^ (r & 7)) << 4);
        cpa16(dst, src, sz);
    }
}

// ---------------- MMA core: warp tile 32x64, A from registers ----------------
__device__ __forceinline__ void compute_chunk(u32 base, const int* boff, const int* bsw,
                                              int ubsel, const uint4 af[2][4], float acc[2][8][4]) {
#pragma unroll
    for (int s = 0; s < 4; ++s) {
        u32 bh[4][4];
#pragma unroll
        for (int nf = 0; nf < 4; ++nf) {
            u32 ub = (u32)(((2 * s + ubsel) ^ bsw[nf]) << 4);
            ldm4(base + boff[nf] + ub, bh[nf]);
        }
#pragma unroll
        for (int mf = 0; mf < 2; ++mf) {
            const u32* a = (const u32*)&af[mf][s];
#pragma unroll
            for (int nb = 0; nb < 8; ++nb)
                mma16816(acc[mf][nb], a, &bh[nb >> 1][(nb & 1) * 2]);
        }
    }
}

__device__ __forceinline__ void bfrag_setup(int wn, int lid, int* boff, int* bsw) {
#pragma unroll
    for (int nf = 0; nf < 4; ++nf) {
        int r = wn * 64 + nf * 16 + (lid & 7) + 8 * (lid >> 4);
        boff[nf] = r * 128; bsw[nf] = r & 7;
    }
}

// 4-stage pipelined main loop; A fragments LDG'd per chunk
#define GEMM_LOOP(WF, XSRC, MODE)                                                   \
    {                                                                               \
        issueB(sb,             XSRC, MODE, 0, b, t0, s_ip, s_if, tid); cpa_commit();\
        issueB(sb + BUFSZ,     XSRC, MODE, 1, b, t0, s_ip, s_if, tid); cpa_commit();\
        issueB(sb + 2 * BUFSZ, XSRC, MODE, 2, b, t0, s_ip, s_if, tid); cpa_commit();\
        for (int kc = 0; kc < NCHK; ++kc) {                                         \
            uint4 af[2][4];                                                         \
            _Pragma("unroll")                                                       \
            for (int mf = 0; mf < 2; ++mf)                                          \
                _Pragma("unroll")                                                   \
                for (int s = 0; s < 4; ++s)                                         \
                    af[mf][s] = WF[wbase + ((mf * 12 + kc) * 4 + s) * 32 + lid];    \
            if (kc <= NCHK - 3)      cpa_wait2();                                   \
            else if (kc == NCHK - 2) cpa_wait1();                                   \
            else                     cpa_wait0();                                   \
            __syncthreads();                                                        \
            if (kc + 3 < NCHK) {                                                    \
                issueB(sb + ((kc + 3) & 3) * BUFSZ, XSRC, MODE, kc + 3, b, t0,      \
                       s_ip, s_if, tid);                                            \
                cpa_commit();                                                       \
            }                                                                       \
            compute_chunk(sb + (kc & 3) * BUFSZ, boff, bsw, ubsel, af, acc);        \
        }                                                                           \
    }

// ---------------- stage 1 GEMM kernel ----------------
__global__ __launch_bounds__(NTHR, 2)
void k1(const float* __restrict__ dfac, const float* __restrict__ bC,
        const float* __restrict__ bP, const float* __restrict__ bF,
        int iter, float dilation) {
    extern __shared__ __align__(1024) unsigned char dynsm[];
    __shared__ int s_ip[128], s_if[128];

    const int tid = threadIdx.x, wid = tid >> 5, lid = tid & 31;
    const int wm = wid & 3, wn = wid >> 2;
    const int b = blockIdx.z, mt = blockIdx.y, t0 = blockIdx.x * 128;
    const u32 sb = sm2u(dynsm);
    const int wbase = ((iter * 2 + mt) * 4 + wm) * 3072;

    if (tid < 128) {
        int t = t0 + tid;
        float dil = dfac[b * TL + t] * dilation;
        int ip = __float2int_rn((float)t - dil);
        int iF = __float2int_rn((float)t + dil);
        s_ip[tid] = (ip >= 0) ? ip : -1;
        s_if[tid] = (iF < TL) ? iF : -1;
    }
    __syncthreads();

    int boff[4], bsw[4];
    int ubsel = (lid >> 3) & 1;
    bfrag_setup(wn, lid, boff, bsw);

    float acc[2][8][4];
#pragma unroll
    for (int a = 0; a < 2; ++a)
#pragma unroll
        for (int c = 0; c < 8; ++c)
#pragma unroll
            for (int d = 0; d < 4; ++d) acc[a][c][d] = 0.f;

    GEMM_LOOP(g_w1f, g_xh, 0)

    // epilogue: bias + lrelu + fp16, transpose via smem, store [t][ch] plane
    __syncthreads();
    u16* ep = (u16*)dynsm;   // [128 cols(t)][132 rows(oc)] u16
    int gq = lid >> 2, cq = 2 * (lid & 3);
#pragma unroll
    for (int mf = 0; mf < 2; ++mf) {
        int r0 = wm * 32 + mf * 16 + gq, r1 = r0 + 8;
        int g0 = mt * 128 + r0, g1 = mt * 128 + r1;
        float bs0 = bC[g0] + bP[g0] + bF[g0];
        float bs1 = bC[g1] + bP[g1] + bF[g1];
#pragma unroll
        for (int nb = 0; nb < 8; ++nb) {
            int c = wn * 64 + nb * 8 + cq;
            const float* a = acc[mf][nb];
            ep[c * 132 + r0]       = h16(lrelu(a[0] + bs0));
            ep[(c + 1) * 132 + r0] = h16(lrelu(a[1] + bs0));
            ep[c * 132 + r1]       = h16(lrelu(a[2] + bs1));
            ep[(c + 1) * 132 + r1] = h16(lrelu(a[3] + bs1));
        }
    }
    __syncthreads();
    u32* yh = (u32*)g_yh;
    const u32* epu = (const u32*)dynsm;
    for (int i = tid; i < 128 * 64; i += NTHR) {
        int t = i >> 6, j = i & 63;
        yh[((size_t)(b * TL + t0 + t)) * 128 + mt * 64 + j] = epu[t * 66 + j];
    }
}

// ---------------- stage 2 GEMM kernel (conv3 + residual + write next-iter xh) ----------------
__global__ __launch_bounds__(NTHR, 2)
void k2(float* __restrict__ xo, const float* __restrict__ bA, int iter) {
    extern __shared__ __align__(1024) unsigned char dynsm[];

    const int tid = threadIdx.x, wid = tid >> 5, lid = tid & 31;
    const int wm = wid & 3, wn = wid >> 2;
    const int b = blockIdx.z, mt = blockIdx.y, t0 = blockIdx.x * 128;
    const u32 sb = sm2u(dynsm);
    const int wbase = ((iter * 2 + mt) * 4 + wm) * 3072;
    const int* s_ip = 0; const int* s_if = 0;   // unused in mode 1

    int boff[4], bsw[4];
    int ubsel = (lid >> 3) & 1;
    bfrag_setup(wn, lid, boff, bsw);

    float acc[2][8][4];
#pragma unroll
    for (int a = 0; a < 2; ++a)
#pragma unroll
        for (int c = 0; c < 8; ++c)
#pragma unroll
            for (int d = 0; d < 4; ++d) acc[a][c][d] = 0.f;

    GEMM_LOOP(g_w2f, g_yh, 1)

    // epilogue: bias + residual -> xo; also lrelu+fp16 transpose -> g_xh (next iter)
    __syncthreads();
    u16* ep = (u16*)dynsm;
    int gq = lid >> 2, cq = 2 * (lid & 3);
#pragma unroll
    for (int mf = 0; mf < 2; ++mf) {
        int r0 = wm * 32 + mf * 16 + gq, r1 = r0 + 8;
        int g0 = mt * 128 + r0, g1 = mt * 128 + r1;
        float bs0 = bA[g0], bs1 = bA[g1];
        float* p0b = xo + ((size_t)(b * CC + g0)) * TL + t0;
        float* p1b = xo + ((size_t)(b * CC + g1)) * TL + t0;
#pragma unroll
        for (int nb = 0; nb < 8; ++nb) {
            int c = wn * 64 + nb * 8 + cq;
            const float* a = acc[mf][nb];
            float2* q0 = (float2*)(p0b + c);
            float2 v0 = *q0;
            v0.x += a[0] + bs0; v0.y += a[1] + bs0;
            *q0 = v0;
            float2* q1 = (float2*)(p1b + c);
            float2 v1 = *q1;
            v1.x += a[2] + bs1; v1.y += a[3] + bs1;
            *q1 = v1;
            ep[c * 132 + r0]       = h16(lrelu(v0.x));
            ep[(c + 1) * 132 + r0] = h16(lrelu(v0.y));
            ep[c * 132 + r1]       = h16(lrelu(v1.x));
            ep[(c + 1) * 132 + r1] = h16(lrelu(v1.y));
        }
    }
    __syncthreads();
    u32* xh = (u32*)g_xh;
    const u32* epu = (const u32*)dynsm;
    for (int i = tid; i < 128 * 64; i += NTHR) {
        int t = i >> 6, j = i & 63;
        xh[((size_t)(b * TL + t0 + t)) * 128 + mt * 64 + j] = epu[t * 66 + j];
    }
}

// ---------------- launch ----------------
extern "C" void kernel_launch(void* const* d_in, const int* in_sizes, int n_in,
                              void* d_out, int out_size) {
    const float* x  = (const float*)d_in[0];
    const float* d  = (const float*)d_in[1];
    const float* WC = (const float*)d_in[2];
    const float* bC = (const float*)d_in[3];
    const float* WP = (const float*)d_in[4];
    const float* bP = (const float*)d_in[5];
    const float* WF = (const float*)d_in[6];
    const float* bF = (const float*)d_in[7];
    const float* WA = (const float*)d_in[8];
    const float* bA = (const float*)d_in[9];
    float* xo = (float*)d_out;

    cudaMemcpyAsync(xo, x, (size_t)BB * CC * TL * sizeof(float),
                    cudaMemcpyDeviceToDevice);

    prep_w<<<576, 256>>>(WC, WP, WF, WA);

    const int DSMEM = NSTG * BUFSZ;   // 64 KB
    cudaFuncSetAttribute((const void*)k1, cudaFuncAttributeMaxDynamicSharedMemorySize, DSMEM);
    cudaFuncSetAttribute((const void*)k2, cudaFuncAttributeMaxDynamicSharedMemorySize, DSMEM);

    dim3 gprex(TL / 32, BB);
    dim3 grid(TL / 128, 2, BB);
    const float dils[3] = {1.0f, 2.0f, 4.0f};
    prex<<<gprex, 256>>>(xo);
    for (int i = 0; i < 3; ++i) {
        k1<<<grid, NTHR, DSMEM>>>(d, bC + i * 256, bP + i * 256, bF + i * 256, i, dils[i]);
        k2<<<grid, NTHR, DSMEM>>>(xo, bA + i * 256, i);
    }
}